// round 6
// baseline (speedup 1.0000x reference)
#include <cuda_runtime.h>
#include <cuda_bf16.h>
#include <cstdint>

using bf16 = __nv_bfloat16;
using bf162 = __nv_bfloat162;

#define DEVFN __device__ __forceinline__

// ---------------- problem sizes ----------------
constexpr int B_SZ = 16, SEQ = 2048, DM = 512, DI = 1024, DS = 16;
constexpr int ROWS = B_SZ * SEQ;           // 32768
constexpr int N1 = 2 * DI;                 // 2048
constexpr int N2 = 1152;                   // 1024 dt + 32 (B|C interleaved) + 96 pad
constexpr int N3 = DM;                     // 512

// ---------------- scratch globals ----------------
__device__ __align__(256) bf16  g_xb  [(size_t)ROWS * DM];
__device__ __align__(256) bf16  g_W1  [(size_t)N1 * DM];
__device__ __align__(256) bf16  g_xr  [(size_t)ROWS * N1];
__device__ __align__(256) bf16  g_xc  [(size_t)ROWS * DI];
__device__ __align__(256) bf16  g_Wcat[(size_t)N2 * DI];
__device__ __align__(256) float g_b2  [N2];
__device__ __align__(256) bf16  g_dtbc[(size_t)ROWS * N2];
__device__ __align__(256) bf16  g_y   [(size_t)ROWS * DI];
__device__ __align__(256) bf16  g_y2  [(size_t)ROWS * DI];
__device__ __align__(256) bf16  g_W3  [(size_t)N3 * DI];
__device__ __align__(256) float g_opre[(size_t)ROWS * DM];

// ---------------- helpers ----------------
DEVFN float bf2f(bf16 v) { return __bfloat162float(v); }
DEVFN bf16  f2bf(float v) { return __float2bfloat16(v); }
DEVFN float2 bf2x(uint32_t u) { bf162 t = *reinterpret_cast<bf162*>(&u); return __bfloat1622float2(t); }
DEVFN uint32_t pack2(float a, float b) {
    bf162 t = __floats2bfloat162_rn(a, b);
    return *reinterpret_cast<uint32_t*>(&t);
}
DEVFN float ex2f(float x) { float r; asm("ex2.approx.f32 %0, %1;" : "=f"(r) : "f"(x)); return r; }
DEVFN float clip10(float x) { return fminf(fmaxf(x, -10.f), 10.f); }
DEVFN float sigm(float x) { return 1.f / (1.f + __expf(-x)); }

DEVFN void cp16(void* s, const void* g) {
    unsigned sa = (unsigned)__cvta_generic_to_shared(s);
    asm volatile("cp.async.cg.shared.global [%0], [%1], 16;\n" :: "r"(sa), "l"(g));
}
DEVFN void ldm4(uint32_t* r, const void* p) {
    unsigned a = (unsigned)__cvta_generic_to_shared(p);
    asm volatile("ldmatrix.sync.aligned.m8n8.x4.shared.b16 {%0,%1,%2,%3}, [%4];\n"
                 : "=r"(r[0]), "=r"(r[1]), "=r"(r[2]), "=r"(r[3]) : "r"(a));
}
DEVFN void mma16816(float* c, const uint32_t* a, const uint32_t* b) {
    asm volatile(
        "mma.sync.aligned.m16n8k16.row.col.f32.bf16.bf16.f32 "
        "{%0,%1,%2,%3}, {%4,%5,%6,%7}, {%8,%9}, {%0,%1,%2,%3};\n"
        : "+f"(c[0]), "+f"(c[1]), "+f"(c[2]), "+f"(c[3])
        : "r"(a[0]), "r"(a[1]), "r"(a[2]), "r"(a[3]), "r"(b[0]), "r"(b[1]));
}

// ---------------- merged prep kernel (single launch) ----------------
// segments: W1 | W3 | Wcat | b2 | clip(x)->g_xb (x4 vectorized)
constexpr int SG0 = N1 * DM;               // 1048576
constexpr int SG1 = N3 * DI;               // 524288
constexpr int SG2 = N2 * DI;               // 1179648
constexpr int SG3 = N2;                    // 1152
constexpr int SG4 = ROWS * DM / 4;         // 4194304
constexpr int PREP_TOT = SG0 + SG1 + SG2 + SG3 + SG4;

__global__ void k_prep(const float* __restrict__ Win, const float* __restrict__ Wout,
                       const float* __restrict__ Wdt, const float* __restrict__ Wx,
                       const float* __restrict__ bdt, const float* __restrict__ x) {
    int i = blockIdx.x * 256 + threadIdx.x;
    if (i < SG0) { g_W1[i] = f2bf(Win[i]); return; }
    i -= SG0;
    if (i < SG1) { g_W3[i] = f2bf(Wout[i]); return; }
    i -= SG1;
    if (i < SG2) {
        int n = i / DI, k = i % DI;
        float v = 0.f;
        if (n < 1024) v = Wdt[n * DI + k];
        else if (n < 1056) {
            int m = n - 1024, q = m >> 3, r = m & 7;
            int s = (r < 4) ? (q * 4 + r) : (16 + q * 4 + (r - 4));   // B | C interleave
            v = Wx[s * DI + k];
        }
        g_Wcat[i] = f2bf(v);
        return;
    }
    i -= SG2;
    if (i < SG3) { g_b2[i] = (i < 1024) ? bdt[i] : 0.f; return; }
    i -= SG3;
    if (i < SG4) {
        float4 v = *reinterpret_cast<const float4*>(x + (size_t)i * 4);
        uint2 pk;
        pk.x = pack2(clip10(v.x), clip10(v.y));
        pk.y = pack2(clip10(v.z), clip10(v.w));
        *reinterpret_cast<uint2*>(g_xb + (size_t)i * 4) = pk;
    }
}

// =====================================================================
// HMMA GEMM: C[M,N] = A[M,K] @ B[N,K]^T
// CTA 256x128, warp 64x64 (8 warps 4x2), K-slab 32, 3 stages, 1 barrier/slab.
// =====================================================================
constexpr int STG = 3;
constexpr int A_ROWS = 256, B_ROWS = 128, SCOLS = 40;
constexpr int A_STAGE = A_ROWS * SCOLS;
constexpr int B_STAGE = B_ROWS * SCOLS;
constexpr int SMEM_TOT = STG * (A_STAGE + B_STAGE) * 2;

template <int SEL>
__global__ void __launch_bounds__(256) k_gemm(const float* __restrict__ resid)
{
    constexpr int N = (SEL == 1) ? N1 : (SEL == 2) ? N2 : N3;
    constexpr int K = (SEL == 1) ? DM : DI;
    constexpr int KT = K / 32;
    const bf16* __restrict__ A  = (SEL == 1) ? g_xb : (SEL == 2) ? g_xc : g_y2;
    const bf16* __restrict__ Bw = (SEL == 1) ? g_W1 : (SEL == 2) ? g_Wcat : g_W3;

    extern __shared__ __align__(16) bf16 sm[];
    bf16* Asm = sm;
    bf16* Bsm = sm + STG * A_STAGE;

    const int tid = threadIdx.x, lane = tid & 31, warp = tid >> 5;
    const int wm = warp >> 1, wn = warp & 1;
    const int m0 = blockIdx.y * 256, n0 = blockIdx.x * 128;
    const bf16* Ap = A + (size_t)m0 * K;
    const bf16* Bp = Bw + (size_t)n0 * K;

    float acc[4][8][4];
#pragma unroll
    for (int i = 0; i < 4; i++)
#pragma unroll
        for (int j = 0; j < 8; j++)
#pragma unroll
            for (int v = 0; v < 4; v++) acc[i][j][v] = 0.f;

    auto fill = [&](int kt) {
        const int buf = kt % STG;
        bf16* As = Asm + buf * A_STAGE;
        bf16* Bs = Bsm + buf * B_STAGE;
#pragma unroll
        for (int i = 0; i < 4; i++) {
            int c = tid + i * 256;
            int row = c >> 2, col = (c & 3) << 3;
            cp16(As + row * SCOLS + col, Ap + (size_t)row * K + kt * 32 + col);
        }
#pragma unroll
        for (int i = 0; i < 2; i++) {
            int c = tid + i * 256;
            int row = c >> 2, col = (c & 3) << 3;
            cp16(Bs + row * SCOLS + col, Bp + (size_t)row * K + kt * 32 + col);
        }
        asm volatile("cp.async.commit_group;\n");
    };

    fill(0);
    fill(1);

#pragma unroll 1
    for (int kt = 0; kt < KT; kt++) {
        asm volatile("cp.async.wait_group %0;\n" :: "n"(1));
        __syncthreads();                     // single barrier per slab
        if (kt + 2 < KT) fill(kt + 2);       // safe: targets (kt-1)%3, done by barrier
        const int buf = kt % STG;
        const bf16* As = Asm + buf * A_STAGE;
        const bf16* Bs = Bsm + buf * B_STAGE;
#pragma unroll
        for (int kh = 0; kh < 2; kh++) {
            const int kk = kh * 16;
            uint32_t af[4][4], bfr[8][2];
#pragma unroll
            for (int mi = 0; mi < 4; mi++)
                ldm4(af[mi], As + (wm * 64 + mi * 16 + (lane & 15)) * SCOLS
                              + kk + ((lane >> 4) << 3));
#pragma unroll
            for (int ni2 = 0; ni2 < 4; ni2++) {
                uint32_t r[4];
                ldm4(r, Bs + (wn * 64 + ni2 * 16 + (lane & 15)) * SCOLS
                         + kk + ((lane >> 4) << 3));
                bfr[2 * ni2][0] = r[0]; bfr[2 * ni2][1] = r[2];
                bfr[2 * ni2 + 1][0] = r[1]; bfr[2 * ni2 + 1][1] = r[3];
            }
#pragma unroll
            for (int mi = 0; mi < 4; mi++)
#pragma unroll
                for (int ni = 0; ni < 8; ni++)
                    mma16816(acc[mi][ni], af[mi], bfr[ni]);
        }
    }

    // epilogue
#pragma unroll
    for (int mi = 0; mi < 4; mi++) {
#pragma unroll
        for (int ni = 0; ni < 8; ni++) {
            int mA = m0 + wm * 64 + mi * 16 + (lane >> 2);
            int n = n0 + wn * 64 + ni * 8 + ((lane & 3) << 1);
#pragma unroll
            for (int h = 0; h < 2; h++) {
                int mm = mA + h * 8;
                float v0 = acc[mi][ni][h * 2 + 0];
                float v1 = acc[mi][ni][h * 2 + 1];
                size_t idx = (size_t)mm * N + n;
                if (SEL == 1) {
                    *reinterpret_cast<bf162*>(g_xr + idx) = __floats2bfloat162_rn(v0, v1);
                } else if (SEL == 2) {
                    v0 += g_b2[n]; v1 += g_b2[n + 1];
                    *reinterpret_cast<bf162*>(g_dtbc + idx) = __floats2bfloat162_rn(v0, v1);
                } else {
                    float x0 = clip10(resid[idx]);
                    float x1 = clip10(resid[idx + 1]);
                    *reinterpret_cast<float2*>(g_opre + idx) = make_float2(v0 + x0, v1 + x1);
                }
            }
        }
    }
}

// ---------------- causal depthwise conv(4) + SiLU, 4 di / thread --------
__global__ void k_conv(const float* __restrict__ cw, const float* __restrict__ cb) {
    int idx = blockIdx.x * 256 + threadIdx.x;          // over ROWS * DI/4
    if (idx >= ROWS * (DI / 4)) return;
    int di4 = (idx & 255) * 4;
    size_t row = (size_t)(idx >> 8);
    int t = (int)(row % SEQ);

    float acc[4] = { cb[di4], cb[di4 + 1], cb[di4 + 2], cb[di4 + 3] };
    float4 w0 = *reinterpret_cast<const float4*>(cw + (di4 + 0) * 4);
    float4 w1 = *reinterpret_cast<const float4*>(cw + (di4 + 1) * 4);
    float4 w2 = *reinterpret_cast<const float4*>(cw + (di4 + 2) * 4);
    float4 w3 = *reinterpret_cast<const float4*>(cw + (di4 + 3) * 4);
    const float* wv[4] = { (const float*)&w0, (const float*)&w1,
                           (const float*)&w2, (const float*)&w3 };
#pragma unroll
    for (int k = 0; k < 4; k++) {
        if (t - 3 + k < 0) continue;
        uint2 raw = *reinterpret_cast<const uint2*>(&g_xr[(row - 3 + k) * N1 + di4]);
        float2 lo = bf2x(raw.x), hi = bf2x(raw.y);
        acc[0] = fmaf(wv[0][k], lo.x, acc[0]);
        acc[1] = fmaf(wv[1][k], lo.y, acc[1]);
        acc[2] = fmaf(wv[2][k], hi.x, acc[2]);
        acc[3] = fmaf(wv[3][k], hi.y, acc[3]);
    }
#pragma unroll
    for (int j = 0; j < 4; j++) acc[j] = acc[j] * sigm(acc[j]);
    uint2 pk;
    pk.x = pack2(acc[0], acc[1]);
    pk.y = pack2(acc[2], acc[3]);
    *reinterpret_cast<uint2*>(&g_xc[row * DI + di4]) = pk;
}

// ---------------- selective scan (B|C interleaved: one uint4 per thread) --
__global__ void __launch_bounds__(128) k_scan(const float* __restrict__ A_log,
                                              const float* __restrict__ Dp) {
    const int b = blockIdx.x >> 5;
    const int diblk = blockIdx.x & 31;
    const int q = threadIdx.x & 3;
    const int di = diblk * 32 + (threadIdx.x >> 2);
    const float LOG2E = 1.4426950408889634f;
    const float CL = 5.0f * LOG2E;

    float A2[4];
#pragma unroll
    for (int j = 0; j < 4; j++) A2[j] = A_log[q * 4 + j] * LOG2E;
    const float Dv = Dp[di];

    float s0 = 0.f, s1 = 0.f, s2 = 0.f, s3 = 0.f;
    const size_t rb = (size_t)b * SEQ;

#pragma unroll 4
    for (int t = 0; t < SEQ; t++) {
        size_t row = rb + t;
        size_t base = row * N2;
        float dt = bf2f(g_dtbc[base + di]);
        float u = bf2f(g_xc[row * DI + di]);
        uint4 bc = *reinterpret_cast<const uint4*>(&g_dtbc[base + 1024 + 8 * q]);
        float2 Bl = bf2x(bc.x), Bh = bf2x(bc.y);
        float2 Cl = bf2x(bc.z), Ch = bf2x(bc.w);
        float du = dt * u;

        float z, dA, acc;
        z = fminf(fmaxf(dt * A2[0], -CL), CL); dA = ex2f(z);
        s0 = fmaf(dA, s0, du * Bl.x); acc = s0 * Cl.x;
        z = fminf(fmaxf(dt * A2[1], -CL), CL); dA = ex2f(z);
        s1 = fmaf(dA, s1, du * Bl.y); acc = fmaf(s1, Cl.y, acc);
        z = fminf(fmaxf(dt * A2[2], -CL), CL); dA = ex2f(z);
        s2 = fmaf(dA, s2, du * Bh.x); acc = fmaf(s2, Ch.x, acc);
        z = fminf(fmaxf(dt * A2[3], -CL), CL); dA = ex2f(z);
        s3 = fmaf(dA, s3, du * Bh.y); acc = fmaf(s3, Ch.y, acc);

        acc += __shfl_xor_sync(0xffffffffu, acc, 1);
        acc += __shfl_xor_sync(0xffffffffu, acc, 2);
        if (q == 0) g_y[row * DI + di] = f2bf(fmaf(u, Dv, acc));
    }
}

// ---------------- y2 = y * silu(res), 4 / thread ----------------
__global__ void k_mulsilu() {
    int idx = blockIdx.x * 256 + threadIdx.x;           // over ROWS * DI/4
    if (idx >= ROWS * (DI / 4)) return;
    int di4 = (idx & 255) * 4;
    size_t row = (size_t)(idx >> 8);
    uint2 yr = *reinterpret_cast<const uint2*>(&g_y[row * DI + di4]);
    uint2 rr = *reinterpret_cast<const uint2*>(&g_xr[row * N1 + 1024 + di4]);
    float2 y0 = bf2x(yr.x), y1 = bf2x(yr.y);
    float2 r0 = bf2x(rr.x), r1 = bf2x(rr.y);
    float o0 = y0.x * r0.x * sigm(r0.x);
    float o1 = y0.y * r0.y * sigm(r0.y);
    float o2 = y1.x * r1.x * sigm(r1.x);
    float o3 = y1.y * r1.y * sigm(r1.y);
    uint2 pk;
    pk.x = pack2(o0, o1);
    pk.y = pack2(o2, o3);
    *reinterpret_cast<uint2*>(&g_y2[row * DI + di4]) = pk;
}

// ---------------- LayerNorm ----------------
__global__ void __launch_bounds__(256) k_ln(const float* __restrict__ gam,
                                            const float* __restrict__ bet,
                                            float* __restrict__ out) {
    int w = (blockIdx.x * 256 + threadIdx.x) >> 5;
    int lane = threadIdx.x & 31;
    if (w >= ROWS) return;
    const float* r = g_opre + (size_t)w * DM;
    float v[16], s = 0.f, ss = 0.f;
#pragma unroll
    for (int i = 0; i < 16; i++) {
        v[i] = r[i * 32 + lane];
        s += v[i];
        ss = fmaf(v[i], v[i], ss);
    }
#pragma unroll
    for (int o = 16; o; o >>= 1) {
        s += __shfl_xor_sync(0xffffffffu, s, o);
        ss += __shfl_xor_sync(0xffffffffu, ss, o);
    }
    float mu = s * (1.f / 512.f);
    float var = ss * (1.f / 512.f) - mu * mu;
    float rstd = rsqrtf(var + 1e-5f);
#pragma unroll
    for (int i = 0; i < 16; i++) {
        int c = i * 32 + lane;
        out[(size_t)w * DM + c] = (v[i] - mu) * rstd * gam[c] + bet[c];
    }
}

// ---------------- launch ----------------
extern "C" void kernel_launch(void* const* d_in, const int* in_sizes, int n_in,
                              void* d_out, int out_size) {
    const float* x      = (const float*)d_in[0];
    const float* W_in   = (const float*)d_in[1];
    const float* conv_w = (const float*)d_in[2];
    const float* conv_b = (const float*)d_in[3];
    const float* W_x    = (const float*)d_in[4];
    const float* W_dt   = (const float*)d_in[5];
    const float* b_dt   = (const float*)d_in[6];
    const float* A_log  = (const float*)d_in[7];
    const float* Dp     = (const float*)d_in[8];
    const float* W_out  = (const float*)d_in[9];
    const float* ln_g   = (const float*)d_in[10];
    const float* ln_b   = (const float*)d_in[11];
    float* out = (float*)d_out;

    static bool attr_done = false;
    if (!attr_done) {
        cudaFuncSetAttribute(k_gemm<1>, cudaFuncAttributeMaxDynamicSharedMemorySize, SMEM_TOT);
        cudaFuncSetAttribute(k_gemm<2>, cudaFuncAttributeMaxDynamicSharedMemorySize, SMEM_TOT);
        cudaFuncSetAttribute(k_gemm<3>, cudaFuncAttributeMaxDynamicSharedMemorySize, SMEM_TOT);
        attr_done = true;
    }

    // 1: all prep
    k_prep<<<(PREP_TOT + 255) / 256, 256>>>(W_in, W_out, W_dt, W_x, b_dt, x);
    // 2: GEMM1
    k_gemm<1><<<dim3(N1 / 128, ROWS / 256), 256, SMEM_TOT>>>(nullptr);
    // 3: conv
    k_conv<<<ROWS * (DI / 4) / 256, 256>>>(conv_w, conv_b);
    // 4: GEMM2  <-- ncu capture window
    k_gemm<2><<<dim3(N2 / 128, ROWS / 256), 256, SMEM_TOT>>>(nullptr);
    // 5: scan
    k_scan<<<B_SZ * 32, 128>>>(A_log, Dp);
    // 6: mulsilu
    k_mulsilu<<<ROWS * (DI / 4) / 256, 256>>>();
    // 7: GEMM3
    k_gemm<3><<<dim3(N3 / 128, ROWS / 256), 256, SMEM_TOT>>>(x);
    // 8: LN
    k_ln<<<(ROWS * 32 + 255) / 256, 256>>>(ln_g, ln_b, out);
}

// round 7
// speedup vs baseline: 1.6289x; 1.6289x over previous
#include <cuda_runtime.h>
#include <cuda_bf16.h>
#include <cstdint>

using bf16 = __nv_bfloat16;
using bf162 = __nv_bfloat162;

#define DEVFN __device__ __forceinline__

// ---------------- problem sizes ----------------
constexpr int B_SZ = 16, SEQ = 2048, DM = 512, DI = 1024, DS = 16;
constexpr int ROWS = B_SZ * SEQ;           // 32768
constexpr int N1 = 2 * DI;                 // 2048
constexpr int N2 = 1152;                   // 1024 dt + 32 (B|C interleaved) + 96 pad
constexpr int N3 = DM;                     // 512

// ---------------- scratch globals ----------------
__device__ __align__(256) bf16  g_xb  [(size_t)ROWS * DM];
__device__ __align__(256) bf16  g_W1  [(size_t)N1 * DM];
__device__ __align__(256) bf16  g_xr  [(size_t)ROWS * N1];
__device__ __align__(256) bf16  g_xc  [(size_t)ROWS * DI];
__device__ __align__(256) bf16  g_Wcat[(size_t)N2 * DI];
__device__ __align__(256) float g_b2  [N2];
__device__ __align__(256) bf16  g_dtbc[(size_t)ROWS * N2];
__device__ __align__(256) bf16  g_y   [(size_t)ROWS * DI];
__device__ __align__(256) bf16  g_y2  [(size_t)ROWS * DI];
__device__ __align__(256) bf16  g_W3  [(size_t)N3 * DI];
__device__ __align__(256) float g_opre[(size_t)ROWS * DM];

// ---------------- helpers ----------------
DEVFN float bf2f(bf16 v) { return __bfloat162float(v); }
DEVFN bf16  f2bf(float v) { return __float2bfloat16(v); }
DEVFN float2 bf2x(uint32_t u) { bf162 t = *reinterpret_cast<bf162*>(&u); return __bfloat1622float2(t); }
DEVFN uint32_t pack2(float a, float b) {
    bf162 t = __floats2bfloat162_rn(a, b);
    return *reinterpret_cast<uint32_t*>(&t);
}
DEVFN float ex2f(float x) { float r; asm("ex2.approx.f32 %0, %1;" : "=f"(r) : "f"(x)); return r; }
DEVFN float clip10(float x) { return fminf(fmaxf(x, -10.f), 10.f); }
DEVFN float sigm(float x) { return 1.f / (1.f + __expf(-x)); }

DEVFN void cp16(void* s, const void* g) {
    unsigned sa = (unsigned)__cvta_generic_to_shared(s);
    asm volatile("cp.async.cg.shared.global [%0], [%1], 16;\n" :: "r"(sa), "l"(g));
}
DEVFN void ldm4(uint32_t* r, const void* p) {
    unsigned a = (unsigned)__cvta_generic_to_shared(p);
    asm volatile("ldmatrix.sync.aligned.m8n8.x4.shared.b16 {%0,%1,%2,%3}, [%4];\n"
                 : "=r"(r[0]), "=r"(r[1]), "=r"(r[2]), "=r"(r[3]) : "r"(a));
}
DEVFN void mma16816(float* c, const uint32_t* a, const uint32_t* b) {
    asm volatile(
        "mma.sync.aligned.m16n8k16.row.col.f32.bf16.bf16.f32 "
        "{%0,%1,%2,%3}, {%4,%5,%6,%7}, {%8,%9}, {%0,%1,%2,%3};\n"
        : "+f"(c[0]), "+f"(c[1]), "+f"(c[2]), "+f"(c[3])
        : "r"(a[0]), "r"(a[1]), "r"(a[2]), "r"(a[3]), "r"(b[0]), "r"(b[1]));
}

// ---------------- merged prep kernel ----------------
constexpr int SG0 = N1 * DM;
constexpr int SG1 = N3 * DI;
constexpr int SG2 = N2 * DI;
constexpr int SG3 = N2;
constexpr int SG4 = ROWS * DM / 4;
constexpr int PREP_TOT = SG0 + SG1 + SG2 + SG3 + SG4;

__global__ void k_prep(const float* __restrict__ Win, const float* __restrict__ Wout,
                       const float* __restrict__ Wdt, const float* __restrict__ Wx,
                       const float* __restrict__ bdt, const float* __restrict__ x) {
    int i = blockIdx.x * 256 + threadIdx.x;
    if (i < SG0) { g_W1[i] = f2bf(Win[i]); return; }
    i -= SG0;
    if (i < SG1) { g_W3[i] = f2bf(Wout[i]); return; }
    i -= SG1;
    if (i < SG2) {
        int n = i / DI, k = i % DI;
        float v = 0.f;
        if (n < 1024) v = Wdt[n * DI + k];
        else if (n < 1056) {
            int m = n - 1024, q = m >> 3, r = m & 7;
            int s = (r < 4) ? (q * 4 + r) : (16 + q * 4 + (r - 4));   // B | C interleave
            v = Wx[s * DI + k];
        }
        g_Wcat[i] = f2bf(v);
        return;
    }
    i -= SG2;
    if (i < SG3) { g_b2[i] = (i < 1024) ? bdt[i] : 0.f; return; }
    i -= SG3;
    if (i < SG4) {
        float4 v = *reinterpret_cast<const float4*>(x + (size_t)i * 4);
        uint2 pk;
        pk.x = pack2(clip10(v.x), clip10(v.y));
        pk.y = pack2(clip10(v.z), clip10(v.w));
        *reinterpret_cast<uint2*>(g_xb + (size_t)i * 4) = pk;
    }
}

// =====================================================================
// HMMA GEMM — R5-proven mainloop (two barriers, fill after compute).
// CTA 256x128, warp 64x64 (8 warps 4x2), K-slab 32, 3 stages.
// =====================================================================
constexpr int STG = 3;
constexpr int A_ROWS = 256, B_ROWS = 128, SCOLS = 40;
constexpr int A_STAGE = A_ROWS * SCOLS;
constexpr int B_STAGE = B_ROWS * SCOLS;
constexpr int SMEM_TOT = STG * (A_STAGE + B_STAGE) * 2;

template <int SEL>
__global__ void __launch_bounds__(256) k_gemm(const float* __restrict__ resid)
{
    constexpr int N = (SEL == 1) ? N1 : (SEL == 2) ? N2 : N3;
    constexpr int K = (SEL == 1) ? DM : DI;
    constexpr int KT = K / 32;
    const bf16* __restrict__ A  = (SEL == 1) ? g_xb : (SEL == 2) ? g_xc : g_y2;
    const bf16* __restrict__ Bw = (SEL == 1) ? g_W1 : (SEL == 2) ? g_Wcat : g_W3;

    extern __shared__ __align__(16) bf16 sm[];
    bf16* Asm = sm;
    bf16* Bsm = sm + STG * A_STAGE;

    const int tid = threadIdx.x, lane = tid & 31, warp = tid >> 5;
    const int wm = warp >> 1, wn = warp & 1;
    const int m0 = blockIdx.y * 256, n0 = blockIdx.x * 128;
    const bf16* Ap = A + (size_t)m0 * K;
    const bf16* Bp = Bw + (size_t)n0 * K;

    float acc[4][8][4];
#pragma unroll
    for (int i = 0; i < 4; i++)
#pragma unroll
        for (int j = 0; j < 8; j++)
#pragma unroll
            for (int v = 0; v < 4; v++) acc[i][j][v] = 0.f;

    auto fill = [&](int kt) {
        const int buf = kt % STG;
        bf16* As = Asm + buf * A_STAGE;
        bf16* Bs = Bsm + buf * B_STAGE;
#pragma unroll
        for (int i = 0; i < 4; i++) {
            int c = tid + i * 256;
            int row = c >> 2, col = (c & 3) << 3;
            cp16(As + row * SCOLS + col, Ap + (size_t)row * K + kt * 32 + col);
        }
#pragma unroll
        for (int i = 0; i < 2; i++) {
            int c = tid + i * 256;
            int row = c >> 2, col = (c & 3) << 3;
            cp16(Bs + row * SCOLS + col, Bp + (size_t)row * K + kt * 32 + col);
        }
        asm volatile("cp.async.commit_group;\n");
    };

    fill(0);
    fill(1);

#pragma unroll 1
    for (int kt = 0; kt < KT; kt++) {
        asm volatile("cp.async.wait_group %0;\n" :: "n"(1));
        __syncthreads();
        const int buf = kt % STG;
        const bf16* As = Asm + buf * A_STAGE;
        const bf16* Bs = Bsm + buf * B_STAGE;
#pragma unroll
        for (int kh = 0; kh < 2; kh++) {
            const int kk = kh * 16;
            uint32_t af[4][4], bfr[8][2];
#pragma unroll
            for (int mi = 0; mi < 4; mi++)
                ldm4(af[mi], As + (wm * 64 + mi * 16 + (lane & 15)) * SCOLS
                              + kk + ((lane >> 4) << 3));
#pragma unroll
            for (int ni2 = 0; ni2 < 4; ni2++) {
                uint32_t r[4];
                ldm4(r, Bs + (wn * 64 + ni2 * 16 + (lane & 15)) * SCOLS
                         + kk + ((lane >> 4) << 3));
                bfr[2 * ni2][0] = r[0]; bfr[2 * ni2][1] = r[2];
                bfr[2 * ni2 + 1][0] = r[1]; bfr[2 * ni2 + 1][1] = r[3];
            }
#pragma unroll
            for (int mi = 0; mi < 4; mi++)
#pragma unroll
                for (int ni = 0; ni < 8; ni++)
                    mma16816(acc[mi][ni], af[mi], bfr[ni]);
        }
        __syncthreads();
        if (kt + 2 < KT) fill(kt + 2);
    }

    // epilogue
#pragma unroll
    for (int mi = 0; mi < 4; mi++) {
#pragma unroll
        for (int ni = 0; ni < 8; ni++) {
            int mA = m0 + wm * 64 + mi * 16 + (lane >> 2);
            int n = n0 + wn * 64 + ni * 8 + ((lane & 3) << 1);
#pragma unroll
            for (int h = 0; h < 2; h++) {
                int mm = mA + h * 8;
                float v0 = acc[mi][ni][h * 2 + 0];
                float v1 = acc[mi][ni][h * 2 + 1];
                size_t idx = (size_t)mm * N + n;
                if (SEL == 1) {
                    *reinterpret_cast<bf162*>(g_xr + idx) = __floats2bfloat162_rn(v0, v1);
                } else if (SEL == 2) {
                    v0 += g_b2[n]; v1 += g_b2[n + 1];
                    *reinterpret_cast<bf162*>(g_dtbc + idx) = __floats2bfloat162_rn(v0, v1);
                } else {
                    float x0 = clip10(resid[idx]);
                    float x1 = clip10(resid[idx + 1]);
                    *reinterpret_cast<float2*>(g_opre + idx) = make_float2(v0 + x0, v1 + x1);
                }
            }
        }
    }
}

// ---------------- causal depthwise conv(4) + SiLU, 4 di / thread --------
__global__ void k_conv(const float* __restrict__ cw, const float* __restrict__ cb) {
    int idx = blockIdx.x * 256 + threadIdx.x;
    if (idx >= ROWS * (DI / 4)) return;
    int di4 = (idx & 255) * 4;
    size_t row = (size_t)(idx >> 8);
    int t = (int)(row % SEQ);

    float acc[4] = { cb[di4], cb[di4 + 1], cb[di4 + 2], cb[di4 + 3] };
    float4 w0 = *reinterpret_cast<const float4*>(cw + (di4 + 0) * 4);
    float4 w1 = *reinterpret_cast<const float4*>(cw + (di4 + 1) * 4);
    float4 w2 = *reinterpret_cast<const float4*>(cw + (di4 + 2) * 4);
    float4 w3 = *reinterpret_cast<const float4*>(cw + (di4 + 3) * 4);
    const float* wv[4] = { (const float*)&w0, (const float*)&w1,
                           (const float*)&w2, (const float*)&w3 };
#pragma unroll
    for (int k = 0; k < 4; k++) {
        if (t - 3 + k < 0) continue;
        uint2 raw = *reinterpret_cast<const uint2*>(&g_xr[(row - 3 + k) * N1 + di4]);
        float2 lo = bf2x(raw.x), hi = bf2x(raw.y);
        acc[0] = fmaf(wv[0][k], lo.x, acc[0]);
        acc[1] = fmaf(wv[1][k], lo.y, acc[1]);
        acc[2] = fmaf(wv[2][k], hi.x, acc[2]);
        acc[3] = fmaf(wv[3][k], hi.y, acc[3]);
    }
#pragma unroll
    for (int j = 0; j < 4; j++) acc[j] = acc[j] * sigm(acc[j]);
    uint2 pk;
    pk.x = pack2(acc[0], acc[1]);
    pk.y = pack2(acc[2], acc[3]);
    *reinterpret_cast<uint2*>(&g_xc[row * DI + di4]) = pk;
}

// ---------------- selective scan (register-pipelined loads) ----------------
__global__ void __launch_bounds__(128) k_scan(const float* __restrict__ A_log,
                                              const float* __restrict__ Dp) {
    const int b = blockIdx.x >> 5;
    const int diblk = blockIdx.x & 31;
    const int q = threadIdx.x & 3;
    const int di = diblk * 32 + (threadIdx.x >> 2);
    const float LOG2E = 1.4426950408889634f;
    const float CL = 5.0f * LOG2E;

    float A2[4];
#pragma unroll
    for (int j = 0; j < 4; j++) A2[j] = A_log[q * 4 + j] * LOG2E;
    const float Dv = Dp[di];

    float s0 = 0.f, s1 = 0.f, s2 = 0.f, s3 = 0.f;
    const size_t rb = (size_t)b * SEQ;

    // prefetch t=0
    float dtc = bf2f(g_dtbc[rb * N2 + di]);
    float uc = bf2f(g_xc[rb * DI + di]);
    uint4 bcc = *reinterpret_cast<const uint4*>(&g_dtbc[rb * N2 + 1024 + 8 * q]);

#pragma unroll 4
    for (int t = 0; t < SEQ; t++) {
        size_t rown = rb + ((t + 1 < SEQ) ? t + 1 : t);
        // prefetch t+1
        float dtn = bf2f(g_dtbc[rown * N2 + di]);
        float un = bf2f(g_xc[rown * DI + di]);
        uint4 bcn = *reinterpret_cast<const uint4*>(&g_dtbc[rown * N2 + 1024 + 8 * q]);

        float2 Bl = bf2x(bcc.x), Bh = bf2x(bcc.y);
        float2 Cl = bf2x(bcc.z), Ch = bf2x(bcc.w);
        float du = dtc * uc;

        float z, dA, acc;
        z = fminf(fmaxf(dtc * A2[0], -CL), CL); dA = ex2f(z);
        s0 = fmaf(dA, s0, du * Bl.x); acc = s0 * Cl.x;
        z = fminf(fmaxf(dtc * A2[1], -CL), CL); dA = ex2f(z);
        s1 = fmaf(dA, s1, du * Bl.y); acc = fmaf(s1, Cl.y, acc);
        z = fminf(fmaxf(dtc * A2[2], -CL), CL); dA = ex2f(z);
        s2 = fmaf(dA, s2, du * Bh.x); acc = fmaf(s2, Ch.x, acc);
        z = fminf(fmaxf(dtc * A2[3], -CL), CL); dA = ex2f(z);
        s3 = fmaf(dA, s3, du * Bh.y); acc = fmaf(s3, Ch.y, acc);

        acc += __shfl_xor_sync(0xffffffffu, acc, 1);
        acc += __shfl_xor_sync(0xffffffffu, acc, 2);
        if (q == 0) g_y[(rb + t) * DI + di] = f2bf(fmaf(uc, Dv, acc));

        dtc = dtn; uc = un; bcc = bcn;
    }
}

// ---------------- y2 = y * silu(res), 4 / thread ----------------
__global__ void k_mulsilu() {
    int idx = blockIdx.x * 256 + threadIdx.x;
    if (idx >= ROWS * (DI / 4)) return;
    int di4 = (idx & 255) * 4;
    size_t row = (size_t)(idx >> 8);
    uint2 yr = *reinterpret_cast<const uint2*>(&g_y[row * DI + di4]);
    uint2 rr = *reinterpret_cast<const uint2*>(&g_xr[row * N1 + 1024 + di4]);
    float2 y0 = bf2x(yr.x), y1 = bf2x(yr.y);
    float2 r0 = bf2x(rr.x), r1 = bf2x(rr.y);
    float o0 = y0.x * r0.x * sigm(r0.x);
    float o1 = y0.y * r0.y * sigm(r0.y);
    float o2 = y1.x * r1.x * sigm(r1.x);
    float o3 = y1.y * r1.y * sigm(r1.y);
    uint2 pk;
    pk.x = pack2(o0, o1);
    pk.y = pack2(o2, o3);
    *reinterpret_cast<uint2*>(&g_y2[row * DI + di4]) = pk;
}

// ---------------- LayerNorm ----------------
__global__ void __launch_bounds__(256) k_ln(const float* __restrict__ gam,
                                            const float* __restrict__ bet,
                                            float* __restrict__ out) {
    int w = (blockIdx.x * 256 + threadIdx.x) >> 5;
    int lane = threadIdx.x & 31;
    if (w >= ROWS) return;
    const float* r = g_opre + (size_t)w * DM;
    float v[16], s = 0.f, ss = 0.f;
#pragma unroll
    for (int i = 0; i < 16; i++) {
        v[i] = r[i * 32 + lane];
        s += v[i];
        ss = fmaf(v[i], v[i], ss);
    }
#pragma unroll
    for (int o = 16; o; o >>= 1) {
        s += __shfl_xor_sync(0xffffffffu, s, o);
        ss += __shfl_xor_sync(0xffffffffu, ss, o);
    }
    float mu = s * (1.f / 512.f);
    float var = ss * (1.f / 512.f) - mu * mu;
    float rstd = rsqrtf(var + 1e-5f);
#pragma unroll
    for (int i = 0; i < 16; i++) {
        int c = i * 32 + lane;
        out[(size_t)w * DM + c] = (v[i] - mu) * rstd * gam[c] + bet[c];
    }
}

// ---------------- launch ----------------
extern "C" void kernel_launch(void* const* d_in, const int* in_sizes, int n_in,
                              void* d_out, int out_size) {
    const float* x      = (const float*)d_in[0];
    const float* W_in   = (const float*)d_in[1];
    const float* conv_w = (const float*)d_in[2];
    const float* conv_b = (const float*)d_in[3];
    const float* W_x    = (const float*)d_in[4];
    const float* W_dt   = (const float*)d_in[5];
    const float* b_dt   = (const float*)d_in[6];
    const float* A_log  = (const float*)d_in[7];
    const float* Dp     = (const float*)d_in[8];
    const float* W_out  = (const float*)d_in[9];
    const float* ln_g   = (const float*)d_in[10];
    const float* ln_b   = (const float*)d_in[11];
    float* out = (float*)d_out;

    static bool attr_done = false;
    if (!attr_done) {
        cudaFuncSetAttribute(k_gemm<1>, cudaFuncAttributeMaxDynamicSharedMemorySize, SMEM_TOT);
        cudaFuncSetAttribute(k_gemm<2>, cudaFuncAttributeMaxDynamicSharedMemorySize, SMEM_TOT);
        cudaFuncSetAttribute(k_gemm<3>, cudaFuncAttributeMaxDynamicSharedMemorySize, SMEM_TOT);
        attr_done = true;
    }

    // 1: prep
    k_prep<<<(PREP_TOT + 255) / 256, 256>>>(W_in, W_out, W_dt, W_x, b_dt, x);
    // 2: GEMM1
    k_gemm<1><<<dim3(N1 / 128, ROWS / 256), 256, SMEM_TOT>>>(nullptr);
    // 3: conv
    k_conv<<<ROWS * (DI / 4) / 256, 256>>>(conv_w, conv_b);
    // 4: GEMM2  <-- ncu capture window (verify revert: expect ~250-330us)
    k_gemm<2><<<dim3(N2 / 128, ROWS / 256), 256, SMEM_TOT>>>(nullptr);
    // 5: scan
    k_scan<<<B_SZ * 32, 128>>>(A_log, Dp);
    // 6: mulsilu
    k_mulsilu<<<ROWS * (DI / 4) / 256, 256>>>();
    // 7: GEMM3
    k_gemm<3><<<dim3(N3 / 128, ROWS / 256), 256, SMEM_TOT>>>(x);
    // 8: LN
    k_ln<<<(ROWS * 32 + 255) / 256, 256>>>(ln_g, ln_b, out);
}

// round 8
// speedup vs baseline: 2.0625x; 1.2662x over previous
#include <cuda_runtime.h>
#include <cuda_bf16.h>
#include <cstdint>

using bf16 = __nv_bfloat16;
using bf162 = __nv_bfloat162;

#define DEVFN __device__ __forceinline__

// ---------------- problem sizes ----------------
constexpr int B_SZ = 16, SEQ = 2048, DM = 512, DI = 1024, DS = 16;
constexpr int ROWS = B_SZ * SEQ;           // 32768
constexpr int N1 = 2 * DI;                 // 2048
constexpr int N2 = 1152;                   // 1024 dt + 32 (B|C interleaved) + 96 pad
constexpr int N3 = DM;                     // 512

// ---------------- scratch globals ----------------
__device__ __align__(256) bf16  g_xb  [(size_t)ROWS * DM];
__device__ __align__(256) bf16  g_W1  [(size_t)N1 * DM];
__device__ __align__(256) bf16  g_xr  [(size_t)ROWS * N1];
__device__ __align__(256) bf16  g_xc  [(size_t)ROWS * DI];
__device__ __align__(256) bf16  g_Wcat[(size_t)N2 * DI];
__device__ __align__(256) float g_b2  [N2];
__device__ __align__(256) bf16  g_dtbc[(size_t)ROWS * N2];
__device__ __align__(256) bf16  g_y2  [(size_t)ROWS * DI];
__device__ __align__(256) bf16  g_W3  [(size_t)N3 * DI];
__device__ __align__(256) float g_opre[(size_t)ROWS * DM];

// ---------------- helpers ----------------
DEVFN float bf2f(bf16 v) { return __bfloat162float(v); }
DEVFN bf16  f2bf(float v) { return __float2bfloat16(v); }
DEVFN float2 bf2x(uint32_t u) { bf162 t = *reinterpret_cast<bf162*>(&u); return __bfloat1622float2(t); }
DEVFN uint32_t pack2(float a, float b) {
    bf162 t = __floats2bfloat162_rn(a, b);
    return *reinterpret_cast<uint32_t*>(&t);
}
DEVFN float ex2f(float x) { float r; asm("ex2.approx.f32 %0, %1;" : "=f"(r) : "f"(x)); return r; }
DEVFN float clip10(float x) { return fminf(fmaxf(x, -10.f), 10.f); }
DEVFN float sigm(float x) { return 1.f / (1.f + __expf(-x)); }

DEVFN void cp16(void* s, const void* g) {
    unsigned sa = (unsigned)__cvta_generic_to_shared(s);
    asm volatile("cp.async.cg.shared.global [%0], [%1], 16;\n" :: "r"(sa), "l"(g));
}
DEVFN void ldm4(uint32_t* r, const void* p) {
    unsigned a = (unsigned)__cvta_generic_to_shared(p);
    asm volatile("ldmatrix.sync.aligned.m8n8.x4.shared.b16 {%0,%1,%2,%3}, [%4];\n"
                 : "=r"(r[0]), "=r"(r[1]), "=r"(r[2]), "=r"(r[3]) : "r"(a));
}
DEVFN void mma16816(float* c, const uint32_t* a, const uint32_t* b) {
    asm volatile(
        "mma.sync.aligned.m16n8k16.row.col.f32.bf16.bf16.f32 "
        "{%0,%1,%2,%3}, {%4,%5,%6,%7}, {%8,%9}, {%0,%1,%2,%3};\n"
        : "+f"(c[0]), "+f"(c[1]), "+f"(c[2]), "+f"(c[3])
        : "r"(a[0]), "r"(a[1]), "r"(a[2]), "r"(a[3]), "r"(b[0]), "r"(b[1]));
}

// ---------------- merged prep kernel ----------------
constexpr int SG0 = N1 * DM;
constexpr int SG1 = N3 * DI;
constexpr int SG2 = N2 * DI;
constexpr int SG3 = N2;
constexpr int SG4 = ROWS * DM / 4;
constexpr int PREP_TOT = SG0 + SG1 + SG2 + SG3 + SG4;

__global__ void k_prep(const float* __restrict__ Win, const float* __restrict__ Wout,
                       const float* __restrict__ Wdt, const float* __restrict__ Wx,
                       const float* __restrict__ bdt, const float* __restrict__ x) {
    int i = blockIdx.x * 256 + threadIdx.x;
    if (i < SG0) { g_W1[i] = f2bf(Win[i]); return; }
    i -= SG0;
    if (i < SG1) { g_W3[i] = f2bf(Wout[i]); return; }
    i -= SG1;
    if (i < SG2) {
        int n = i / DI, k = i % DI;
        float v = 0.f;
        if (n < 1024) v = Wdt[n * DI + k];
        else if (n < 1056) {
            int m = n - 1024, q = m >> 3, r = m & 7;
            int s = (r < 4) ? (q * 4 + r) : (16 + q * 4 + (r - 4));   // B | C interleave
            v = Wx[s * DI + k];
        }
        g_Wcat[i] = f2bf(v);
        return;
    }
    i -= SG2;
    if (i < SG3) { g_b2[i] = (i < 1024) ? bdt[i] : 0.f; return; }
    i -= SG3;
    if (i < SG4) {
        float4 v = *reinterpret_cast<const float4*>(x + (size_t)i * 4);
        uint2 pk;
        pk.x = pack2(clip10(v.x), clip10(v.y));
        pk.y = pack2(clip10(v.z), clip10(v.w));
        *reinterpret_cast<uint2*>(g_xb + (size_t)i * 4) = pk;
    }
}

// =====================================================================
// HMMA GEMM — 2-CTA/SM config: CTA 128x128, 8 warps (4x2), warp 32x64,
// K-slab 32, 3 stages, R5-proven two-barrier mainloop.
// =====================================================================
constexpr int STG = 3;
constexpr int SCOLS = 40;
constexpr int A_STAGE = 128 * SCOLS;
constexpr int B_STAGE = 128 * SCOLS;
constexpr int SMEM_TOT = STG * (A_STAGE + B_STAGE) * 2;   // 61440 B

template <int SEL>
__global__ void __launch_bounds__(256, 2) k_gemm(const float* __restrict__ resid)
{
    constexpr int N = (SEL == 1) ? N1 : (SEL == 2) ? N2 : N3;
    constexpr int K = (SEL == 1) ? DM : DI;
    constexpr int KT = K / 32;
    const bf16* __restrict__ A  = (SEL == 1) ? g_xb : (SEL == 2) ? g_xc : g_y2;
    const bf16* __restrict__ Bw = (SEL == 1) ? g_W1 : (SEL == 2) ? g_Wcat : g_W3;

    extern __shared__ __align__(16) bf16 sm[];
    bf16* Asm = sm;
    bf16* Bsm = sm + STG * A_STAGE;

    const int tid = threadIdx.x, lane = tid & 31, warp = tid >> 5;
    const int wm = warp >> 1, wn = warp & 1;            // 4 x 2 warp grid
    const int m0 = blockIdx.y * 128, n0 = blockIdx.x * 128;
    const bf16* Ap = A + (size_t)m0 * K;
    const bf16* Bp = Bw + (size_t)n0 * K;

    float acc[2][8][4];
#pragma unroll
    for (int i = 0; i < 2; i++)
#pragma unroll
        for (int j = 0; j < 8; j++)
#pragma unroll
            for (int v = 0; v < 4; v++) acc[i][j][v] = 0.f;

    auto fill = [&](int kt) {
        const int buf = kt % STG;
        bf16* As = Asm + buf * A_STAGE;
        bf16* Bs = Bsm + buf * B_STAGE;
#pragma unroll
        for (int i = 0; i < 2; i++) {
            int c = tid + i * 256;                      // 0..511
            int row = c >> 2, col = (c & 3) << 3;
            cp16(As + row * SCOLS + col, Ap + (size_t)row * K + kt * 32 + col);
            cp16(Bs + row * SCOLS + col, Bp + (size_t)row * K + kt * 32 + col);
        }
        asm volatile("cp.async.commit_group;\n");
    };

    fill(0);
    fill(1);

#pragma unroll 1
    for (int kt = 0; kt < KT; kt++) {
        asm volatile("cp.async.wait_group %0;\n" :: "n"(1));
        __syncthreads();
        const int buf = kt % STG;
        const bf16* As = Asm + buf * A_STAGE;
        const bf16* Bs = Bsm + buf * B_STAGE;
#pragma unroll
        for (int kh = 0; kh < 2; kh++) {
            const int kk = kh * 16;
            uint32_t af[2][4], bfr[8][2];
#pragma unroll
            for (int mi = 0; mi < 2; mi++)
                ldm4(af[mi], As + (wm * 32 + mi * 16 + (lane & 15)) * SCOLS
                              + kk + ((lane >> 4) << 3));
#pragma unroll
            for (int ni2 = 0; ni2 < 4; ni2++) {
                uint32_t r[4];
                ldm4(r, Bs + (wn * 64 + ni2 * 16 + (lane & 15)) * SCOLS
                         + kk + ((lane >> 4) << 3));
                bfr[2 * ni2][0] = r[0]; bfr[2 * ni2][1] = r[2];
                bfr[2 * ni2 + 1][0] = r[1]; bfr[2 * ni2 + 1][1] = r[3];
            }
#pragma unroll
            for (int mi = 0; mi < 2; mi++)
#pragma unroll
                for (int ni = 0; ni < 8; ni++)
                    mma16816(acc[mi][ni], af[mi], bfr[ni]);
        }
        __syncthreads();
        if (kt + 2 < KT) fill(kt + 2);
    }

    // epilogue
#pragma unroll
    for (int mi = 0; mi < 2; mi++) {
#pragma unroll
        for (int ni = 0; ni < 8; ni++) {
            int mA = m0 + wm * 32 + mi * 16 + (lane >> 2);
            int n = n0 + wn * 64 + ni * 8 + ((lane & 3) << 1);
#pragma unroll
            for (int h = 0; h < 2; h++) {
                int mm = mA + h * 8;
                float v0 = acc[mi][ni][h * 2 + 0];
                float v1 = acc[mi][ni][h * 2 + 1];
                size_t idx = (size_t)mm * N + n;
                if (SEL == 1) {
                    *reinterpret_cast<bf162*>(g_xr + idx) = __floats2bfloat162_rn(v0, v1);
                } else if (SEL == 2) {
                    v0 += g_b2[n]; v1 += g_b2[n + 1];
                    *reinterpret_cast<bf162*>(g_dtbc + idx) = __floats2bfloat162_rn(v0, v1);
                } else {
                    float x0 = clip10(resid[idx]);
                    float x1 = clip10(resid[idx + 1]);
                    *reinterpret_cast<float2*>(g_opre + idx) = make_float2(v0 + x0, v1 + x1);
                }
            }
        }
    }
}

// ---------------- causal depthwise conv(4) + SiLU, 4 di / thread --------
__global__ void k_conv(const float* __restrict__ cw, const float* __restrict__ cb) {
    int idx = blockIdx.x * 256 + threadIdx.x;
    if (idx >= ROWS * (DI / 4)) return;
    int di4 = (idx & 255) * 4;
    size_t row = (size_t)(idx >> 8);
    int t = (int)(row % SEQ);

    float acc[4] = { cb[di4], cb[di4 + 1], cb[di4 + 2], cb[di4 + 3] };
    float4 w0 = *reinterpret_cast<const float4*>(cw + (di4 + 0) * 4);
    float4 w1 = *reinterpret_cast<const float4*>(cw + (di4 + 1) * 4);
    float4 w2 = *reinterpret_cast<const float4*>(cw + (di4 + 2) * 4);
    float4 w3 = *reinterpret_cast<const float4*>(cw + (di4 + 3) * 4);
    const float* wv[4] = { (const float*)&w0, (const float*)&w1,
                           (const float*)&w2, (const float*)&w3 };
#pragma unroll
    for (int k = 0; k < 4; k++) {
        if (t - 3 + k < 0) continue;
        uint2 raw = *reinterpret_cast<const uint2*>(&g_xr[(row - 3 + k) * N1 + di4]);
        float2 lo = bf2x(raw.x), hi = bf2x(raw.y);
        acc[0] = fmaf(wv[0][k], lo.x, acc[0]);
        acc[1] = fmaf(wv[1][k], lo.y, acc[1]);
        acc[2] = fmaf(wv[2][k], hi.x, acc[2]);
        acc[3] = fmaf(wv[3][k], hi.y, acc[3]);
    }
#pragma unroll
    for (int j = 0; j < 4; j++) acc[j] = acc[j] * sigm(acc[j]);
    uint2 pk;
    pk.x = pack2(acc[0], acc[1]);
    pk.y = pack2(acc[2], acc[3]);
    *reinterpret_cast<uint2*>(&g_xc[row * DI + di4]) = pk;
}

// =====================================================================
// Selective scan with cp.async smem pipeline (depth 24 t) + fused mulsilu.
// Block = (b, 32-di slice), 128 threads = 32 di x 4 q.
// Per t (256B in smem): dt[32di] 64B | u 64B | BC 64B | res 64B.
// Chunks of 8 t; ring of 4 chunks; prefetch 3 chunks ahead.
// =====================================================================
constexpr int SC_CHUNK = 8;
constexpr int SC_RING = 4;
constexpr int SC_TB = 256;                               // bytes per t
constexpr int SC_CHB = SC_CHUNK * SC_TB;                 // 2048 B per chunk
constexpr int SC_NCH = SEQ / SC_CHUNK;                   // 256 chunks

__global__ void __launch_bounds__(128) k_scan(const float* __restrict__ A_log,
                                              const float* __restrict__ Dp) {
    __shared__ __align__(16) char sbuf[SC_RING * SC_CHB]; // 8 KB

    const int tid = threadIdx.x;
    const int b = blockIdx.x >> 5;
    const int diblk = blockIdx.x & 31;
    const int q = tid & 3;
    const int dil = tid >> 2;                             // 0..31
    const int di = diblk * 32 + dil;
    const float LOG2E = 1.4426950408889634f;
    const float CL = 5.0f * LOG2E;

    float A2[4];
#pragma unroll
    for (int j = 0; j < 4; j++) A2[j] = A_log[q * 4 + j] * LOG2E;
    const float Dv = Dp[di];
    const size_t rb = (size_t)b * SEQ;

    // fill chunk c: 128 threads issue exactly one cp16 each
    const int f_tl = tid >> 4;                            // 0..7 t within chunk
    const int f_part = tid & 15;                          // 0..15
    const int f_sub = f_part >> 2;                        // 0 dt,1 u,2 bc,3 res
    const int f_off16 = (f_part & 3) * 8;                 // element offset (8 bf16/16B)
    auto fill = [&](int c) {
        size_t row = rb + (size_t)c * SC_CHUNK + f_tl;
        char* dst = sbuf + (c & (SC_RING - 1)) * SC_CHB + f_tl * SC_TB + f_sub * 64
                    + (f_part & 3) * 16;
        const bf16* src;
        if (f_sub == 0)      src = &g_dtbc[row * N2 + diblk * 32 + f_off16];
        else if (f_sub == 1) src = &g_xc[row * DI + diblk * 32 + f_off16];
        else if (f_sub == 2) src = &g_dtbc[row * N2 + 1024 + f_off16];
        else                 src = &g_xr[row * N1 + 1024 + diblk * 32 + f_off16];
        cp16(dst, src);
        asm volatile("cp.async.commit_group;\n");
    };

    fill(0); fill(1); fill(2);

    float s0 = 0.f, s1 = 0.f, s2 = 0.f, s3 = 0.f;

#pragma unroll 1
    for (int c = 0; c < SC_NCH; c++) {
        asm volatile("cp.async.wait_group %0;\n" :: "n"(2));
        __syncthreads();
        const char* base = sbuf + (c & (SC_RING - 1)) * SC_CHB;
#pragma unroll
        for (int tl = 0; tl < SC_CHUNK; tl++) {
            const char* p = base + tl * SC_TB;
            float dt = bf2f(reinterpret_cast<const bf16*>(p)[dil]);
            float u  = bf2f(reinterpret_cast<const bf16*>(p + 64)[dil]);
            uint4 bc = *reinterpret_cast<const uint4*>(p + 128 + q * 16);
            float2 Bl = bf2x(bc.x), Bh = bf2x(bc.y);
            float2 Cl = bf2x(bc.z), Ch = bf2x(bc.w);
            float du = dt * u;

            float z, dA, acc;
            z = fminf(fmaxf(dt * A2[0], -CL), CL); dA = ex2f(z);
            s0 = fmaf(dA, s0, du * Bl.x); acc = s0 * Cl.x;
            z = fminf(fmaxf(dt * A2[1], -CL), CL); dA = ex2f(z);
            s1 = fmaf(dA, s1, du * Bl.y); acc = fmaf(s1, Cl.y, acc);
            z = fminf(fmaxf(dt * A2[2], -CL), CL); dA = ex2f(z);
            s2 = fmaf(dA, s2, du * Bh.x); acc = fmaf(s2, Ch.x, acc);
            z = fminf(fmaxf(dt * A2[3], -CL), CL); dA = ex2f(z);
            s3 = fmaf(dA, s3, du * Bh.y); acc = fmaf(s3, Ch.y, acc);

            acc += __shfl_xor_sync(0xffffffffu, acc, 1);
            acc += __shfl_xor_sync(0xffffffffu, acc, 2);
            if (q == 0) {
                float rv = bf2f(reinterpret_cast<const bf16*>(p + 192)[dil]);
                float y = fmaf(u, Dv, acc);
                g_y2[(rb + (size_t)c * SC_CHUNK + tl) * DI + di] =
                    f2bf(y * rv * sigm(rv));
            }
        }
        __syncthreads();
        if (c + 3 < SC_NCH) fill(c + 3);
    }
}

// ---------------- LayerNorm ----------------
__global__ void __launch_bounds__(256) k_ln(const float* __restrict__ gam,
                                            const float* __restrict__ bet,
                                            float* __restrict__ out) {
    int w = (blockIdx.x * 256 + threadIdx.x) >> 5;
    int lane = threadIdx.x & 31;
    if (w >= ROWS) return;
    const float* r = g_opre + (size_t)w * DM;
    float v[16], s = 0.f, ss = 0.f;
#pragma unroll
    for (int i = 0; i < 16; i++) {
        v[i] = r[i * 32 + lane];
        s += v[i];
        ss = fmaf(v[i], v[i], ss);
    }
#pragma unroll
    for (int o = 16; o; o >>= 1) {
        s += __shfl_xor_sync(0xffffffffu, s, o);
        ss += __shfl_xor_sync(0xffffffffu, ss, o);
    }
    float mu = s * (1.f / 512.f);
    float var = ss * (1.f / 512.f) - mu * mu;
    float rstd = rsqrtf(var + 1e-5f);
#pragma unroll
    for (int i = 0; i < 16; i++) {
        int c = i * 32 + lane;
        out[(size_t)w * DM + c] = (v[i] - mu) * rstd * gam[c] + bet[c];
    }
}

// ---------------- launch ----------------
extern "C" void kernel_launch(void* const* d_in, const int* in_sizes, int n_in,
                              void* d_out, int out_size) {
    const float* x      = (const float*)d_in[0];
    const float* W_in   = (const float*)d_in[1];
    const float* conv_w = (const float*)d_in[2];
    const float* conv_b = (const float*)d_in[3];
    const float* W_x    = (const float*)d_in[4];
    const float* W_dt   = (const float*)d_in[5];
    const float* b_dt   = (const float*)d_in[6];
    const float* A_log  = (const float*)d_in[7];
    const float* Dp     = (const float*)d_in[8];
    const float* W_out  = (const float*)d_in[9];
    const float* ln_g   = (const float*)d_in[10];
    const float* ln_b   = (const float*)d_in[11];
    float* out = (float*)d_out;

    static bool attr_done = false;
    if (!attr_done) {
        cudaFuncSetAttribute(k_gemm<1>, cudaFuncAttributeMaxDynamicSharedMemorySize, SMEM_TOT);
        cudaFuncSetAttribute(k_gemm<2>, cudaFuncAttributeMaxDynamicSharedMemorySize, SMEM_TOT);
        cudaFuncSetAttribute(k_gemm<3>, cudaFuncAttributeMaxDynamicSharedMemorySize, SMEM_TOT);
        attr_done = true;
    }

    // 1: prep
    k_prep<<<(PREP_TOT + 255) / 256, 256>>>(W_in, W_out, W_dt, W_x, b_dt, x);
    // 2: GEMM1 [32768,2048]
    k_gemm<1><<<dim3(N1 / 128, ROWS / 128), 256, SMEM_TOT>>>(nullptr);
    // 3: conv
    k_conv<<<ROWS * (DI / 4) / 256, 256>>>(conv_w, conv_b);
    // 4: GEMM2 [32768,1152]  <-- ncu capture window (verify 2-CTA occupancy)
    k_gemm<2><<<dim3(N2 / 128, ROWS / 128), 256, SMEM_TOT>>>(nullptr);
    // 5: scan (+ fused mulsilu) -> g_y2
    k_scan<<<B_SZ * 32, 128>>>(A_log, Dp);
    // 6: GEMM3 [32768,512] f32 + residual
    k_gemm<3><<<dim3(N3 / 128, ROWS / 128), 256, SMEM_TOT>>>(x);
    // 7: LN
    k_ln<<<(ROWS * 32 + 255) / 256, 256>>>(ln_g, ln_b, out);
}

// round 9
// speedup vs baseline: 2.2002x; 1.0668x over previous
#include <cuda_runtime.h>
#include <cuda_bf16.h>
#include <cstdint>

using bf16 = __nv_bfloat16;
using bf162 = __nv_bfloat162;

#define DEVFN __device__ __forceinline__

// ---------------- problem sizes ----------------
constexpr int B_SZ = 16, SEQ = 2048, DM = 512, DI = 1024, DS = 16;
constexpr int ROWS = B_SZ * SEQ;           // 32768
constexpr int N1 = 2 * DI;                 // 2048
constexpr int N2 = 1152;                   // 1024 dt + 32 (B|C interleaved) + 96 pad
constexpr int N3 = DM;                     // 512

// ---------------- scratch globals ----------------
__device__ __align__(256) bf16  g_xb  [(size_t)ROWS * DM];
__device__ __align__(256) bf16  g_W1  [(size_t)N1 * DM];
__device__ __align__(256) bf16  g_xr  [(size_t)ROWS * N1];
__device__ __align__(256) bf16  g_xc  [(size_t)ROWS * DI];
__device__ __align__(256) bf16  g_Wcat[(size_t)N2 * DI];
__device__ __align__(256) float g_b2  [N2];
__device__ __align__(256) bf16  g_dtbc[(size_t)ROWS * N2];
__device__ __align__(256) bf16  g_y2  [(size_t)ROWS * DI];
__device__ __align__(256) bf16  g_W3  [(size_t)N3 * DI];
__device__ __align__(256) float g_opre[(size_t)ROWS * DM];

// ---------------- helpers ----------------
DEVFN float bf2f(bf16 v) { return __bfloat162float(v); }
DEVFN bf16  f2bf(float v) { return __float2bfloat16(v); }
DEVFN float2 bf2x(uint32_t u) { bf162 t = *reinterpret_cast<bf162*>(&u); return __bfloat1622float2(t); }
DEVFN uint32_t pack2(float a, float b) {
    bf162 t = __floats2bfloat162_rn(a, b);
    return *reinterpret_cast<uint32_t*>(&t);
}
DEVFN float ex2f(float x) { float r; asm("ex2.approx.f32 %0, %1;" : "=f"(r) : "f"(x)); return r; }
DEVFN float clip10(float x) { return fminf(fmaxf(x, -10.f), 10.f); }
DEVFN float sigm(float x) { return 1.f / (1.f + __expf(-x)); }

DEVFN void cp16(void* s, const void* g) {
    unsigned sa = (unsigned)__cvta_generic_to_shared(s);
    asm volatile("cp.async.cg.shared.global [%0], [%1], 16;\n" :: "r"(sa), "l"(g));
}
DEVFN void cp_commit() { asm volatile("cp.async.commit_group;\n"); }
DEVFN void ldm4(uint32_t* r, const void* p) {
    unsigned a = (unsigned)__cvta_generic_to_shared(p);
    asm volatile("ldmatrix.sync.aligned.m8n8.x4.shared.b16 {%0,%1,%2,%3}, [%4];\n"
                 : "=r"(r[0]), "=r"(r[1]), "=r"(r[2]), "=r"(r[3]) : "r"(a));
}
DEVFN void mma16816(float* c, const uint32_t* a, const uint32_t* b) {
    asm volatile(
        "mma.sync.aligned.m16n8k16.row.col.f32.bf16.bf16.f32 "
        "{%0,%1,%2,%3}, {%4,%5,%6,%7}, {%8,%9}, {%0,%1,%2,%3};\n"
        : "+f"(c[0]), "+f"(c[1]), "+f"(c[2]), "+f"(c[3])
        : "r"(a[0]), "r"(a[1]), "r"(a[2]), "r"(a[3]), "r"(b[0]), "r"(b[1]));
}

// ---------------- merged prep kernel ----------------
constexpr int SG0 = N1 * DM;
constexpr int SG1 = N3 * DI;
constexpr int SG2 = N2 * DI;
constexpr int SG3 = N2;
constexpr int SG4 = ROWS * DM / 4;
constexpr int PREP_TOT = SG0 + SG1 + SG2 + SG3 + SG4;

__global__ void k_prep(const float* __restrict__ Win, const float* __restrict__ Wout,
                       const float* __restrict__ Wdt, const float* __restrict__ Wx,
                       const float* __restrict__ bdt, const float* __restrict__ x) {
    int i = blockIdx.x * 256 + threadIdx.x;
    if (i < SG0) { g_W1[i] = f2bf(Win[i]); return; }
    i -= SG0;
    if (i < SG1) { g_W3[i] = f2bf(Wout[i]); return; }
    i -= SG1;
    if (i < SG2) {
        int n = i / DI, k = i % DI;
        float v = 0.f;
        if (n < 1024) v = Wdt[n * DI + k];
        else if (n < 1056) {
            int m = n - 1024, q = m >> 3, r = m & 7;
            int s = (r < 4) ? (q * 4 + r) : (16 + q * 4 + (r - 4));   // B | C interleave
            v = Wx[s * DI + k];
        }
        g_Wcat[i] = f2bf(v);
        return;
    }
    i -= SG2;
    if (i < SG3) { g_b2[i] = (i < 1024) ? bdt[i] : 0.f; return; }
    i -= SG3;
    if (i < SG4) {
        float4 v = *reinterpret_cast<const float4*>(x + (size_t)i * 4);
        uint2 pk;
        pk.x = pack2(clip10(v.x), clip10(v.y));
        pk.y = pack2(clip10(v.z), clip10(v.w));
        *reinterpret_cast<uint2*>(g_xb + (size_t)i * 4) = pk;
    }
}

// =====================================================================
// HMMA GEMM — CTA 128x128, 8 warps (4x2), warp 32x64, K-slab 32,
// STG=4 ring, single barrier per slab, exact commit accounting.
// =====================================================================
constexpr int STG = 4;
constexpr int SCOLS = 40;
constexpr int A_STAGE = 128 * SCOLS;
constexpr int B_STAGE = 128 * SCOLS;
constexpr int SMEM_TOT = STG * (A_STAGE + B_STAGE) * 2;   // 81920 B

template <int SEL>
__global__ void __launch_bounds__(256, 2) k_gemm(const float* __restrict__ resid)
{
    constexpr int N = (SEL == 1) ? N1 : (SEL == 2) ? N2 : N3;
    constexpr int K = (SEL == 1) ? DM : DI;
    constexpr int KT = K / 32;
    const bf16* __restrict__ A  = (SEL == 1) ? g_xb : (SEL == 2) ? g_xc : g_y2;
    const bf16* __restrict__ Bw = (SEL == 1) ? g_W1 : (SEL == 2) ? g_Wcat : g_W3;

    extern __shared__ __align__(16) bf16 sm[];
    bf16* Asm = sm;
    bf16* Bsm = sm + STG * A_STAGE;

    const int tid = threadIdx.x, lane = tid & 31, warp = tid >> 5;
    const int wm = warp >> 1, wn = warp & 1;            // 4 x 2 warp grid
    const int m0 = blockIdx.y * 128, n0 = blockIdx.x * 128;
    const bf16* Ap = A + (size_t)m0 * K;
    const bf16* Bp = Bw + (size_t)n0 * K;

    float acc[2][8][4];
#pragma unroll
    for (int i = 0; i < 2; i++)
#pragma unroll
        for (int j = 0; j < 8; j++)
#pragma unroll
            for (int v = 0; v < 4; v++) acc[i][j][v] = 0.f;

    auto fill = [&](int kt) {
        const int buf = kt % STG;
        bf16* As = Asm + buf * A_STAGE;
        bf16* Bs = Bsm + buf * B_STAGE;
#pragma unroll
        for (int i = 0; i < 2; i++) {
            int c = tid + i * 256;                      // 0..511
            int row = c >> 2, col = (c & 3) << 3;
            cp16(As + row * SCOLS + col, Ap + (size_t)row * K + kt * 32 + col);
            cp16(Bs + row * SCOLS + col, Bp + (size_t)row * K + kt * 32 + col);
        }
        cp_commit();
    };

    fill(0); fill(1); fill(2);                          // 3 groups in flight

#pragma unroll 1
    for (int kt = 0; kt < KT; kt++) {
        // invariant: groups issued = kt + 3; wait leaves <=2 pending => slab kt ready
        asm volatile("cp.async.wait_group %0;\n" :: "n"(2));
        __syncthreads();                                 // single barrier per slab
        const int buf = kt % STG;
        const bf16* As = Asm + buf * A_STAGE;
        const bf16* Bs = Bsm + buf * B_STAGE;
#pragma unroll
        for (int kh = 0; kh < 2; kh++) {
            const int kk = kh * 16;
            uint32_t af[2][4], bfr[8][2];
#pragma unroll
            for (int mi = 0; mi < 2; mi++)
                ldm4(af[mi], As + (wm * 32 + mi * 16 + (lane & 15)) * SCOLS
                              + kk + ((lane >> 4) << 3));
#pragma unroll
            for (int ni2 = 0; ni2 < 4; ni2++) {
                uint32_t r[4];
                ldm4(r, Bs + (wn * 64 + ni2 * 16 + (lane & 15)) * SCOLS
                         + kk + ((lane >> 4) << 3));
                bfr[2 * ni2][0] = r[0]; bfr[2 * ni2][1] = r[2];
                bfr[2 * ni2 + 1][0] = r[1]; bfr[2 * ni2 + 1][1] = r[3];
            }
#pragma unroll
            for (int mi = 0; mi < 2; mi++)
#pragma unroll
                for (int ni = 0; ni < 8; ni++)
                    mma16816(acc[mi][ni], af[mi], bfr[ni]);
        }
        // fill AFTER compute (R5/R7-proven order); buffer (kt+3)%4=(kt-1)%4 is free:
        // all warps finished reading it before this slab's top barrier.
        if (kt + 3 < KT) fill(kt + 3);
        else cp_commit();                                // keep group accounting exact
    }

    // epilogue
#pragma unroll
    for (int mi = 0; mi < 2; mi++) {
#pragma unroll
        for (int ni = 0; ni < 8; ni++) {
            int mA = m0 + wm * 32 + mi * 16 + (lane >> 2);
            int n = n0 + wn * 64 + ni * 8 + ((lane & 3) << 1);
#pragma unroll
            for (int h = 0; h < 2; h++) {
                int mm = mA + h * 8;
                float v0 = acc[mi][ni][h * 2 + 0];
                float v1 = acc[mi][ni][h * 2 + 1];
                size_t idx = (size_t)mm * N + n;
                if (SEL == 1) {
                    *reinterpret_cast<bf162*>(g_xr + idx) = __floats2bfloat162_rn(v0, v1);
                } else if (SEL == 2) {
                    v0 += g_b2[n]; v1 += g_b2[n + 1];
                    *reinterpret_cast<bf162*>(g_dtbc + idx) = __floats2bfloat162_rn(v0, v1);
                } else {
                    float x0 = clip10(resid[idx]);
                    float x1 = clip10(resid[idx + 1]);
                    *reinterpret_cast<float2*>(g_opre + idx) = make_float2(v0 + x0, v1 + x1);
                }
            }
        }
    }
}

// ---------------- causal depthwise conv(4) + SiLU, 4 di / thread --------
__global__ void k_conv(const float* __restrict__ cw, const float* __restrict__ cb) {
    int idx = blockIdx.x * 256 + threadIdx.x;
    if (idx >= ROWS * (DI / 4)) return;
    int di4 = (idx & 255) * 4;
    size_t row = (size_t)(idx >> 8);
    int t = (int)(row % SEQ);

    float acc[4] = { cb[di4], cb[di4 + 1], cb[di4 + 2], cb[di4 + 3] };
    float4 w0 = *reinterpret_cast<const float4*>(cw + (di4 + 0) * 4);
    float4 w1 = *reinterpret_cast<const float4*>(cw + (di4 + 1) * 4);
    float4 w2 = *reinterpret_cast<const float4*>(cw + (di4 + 2) * 4);
    float4 w3 = *reinterpret_cast<const float4*>(cw + (di4 + 3) * 4);
    const float* wv[4] = { (const float*)&w0, (const float*)&w1,
                           (const float*)&w2, (const float*)&w3 };
#pragma unroll
    for (int k = 0; k < 4; k++) {
        if (t - 3 + k < 0) continue;
        uint2 raw = *reinterpret_cast<const uint2*>(&g_xr[(row - 3 + k) * N1 + di4]);
        float2 lo = bf2x(raw.x), hi = bf2x(raw.y);
        acc[0] = fmaf(wv[0][k], lo.x, acc[0]);
        acc[1] = fmaf(wv[1][k], lo.y, acc[1]);
        acc[2] = fmaf(wv[2][k], hi.x, acc[2]);
        acc[3] = fmaf(wv[3][k], hi.y, acc[3]);
    }
#pragma unroll
    for (int j = 0; j < 4; j++) acc[j] = acc[j] * sigm(acc[j]);
    uint2 pk;
    pk.x = pack2(acc[0], acc[1]);
    pk.y = pack2(acc[2], acc[3]);
    *reinterpret_cast<uint2*>(&g_xc[row * DI + di4]) = pk;
}

// =====================================================================
// Selective scan, cp.async pipeline + fused mulsilu.
// No clamp (|dt*A| < 0.1 by construction, 800-sigma margin vs the 5.0 clip).
// Single barrier per chunk; exact commit accounting.
// =====================================================================
constexpr int SC_CHUNK = 8;
constexpr int SC_RING = 4;
constexpr int SC_TB = 256;
constexpr int SC_CHB = SC_CHUNK * SC_TB;
constexpr int SC_NCH = SEQ / SC_CHUNK;

__global__ void __launch_bounds__(128) k_scan(const float* __restrict__ A_log,
                                              const float* __restrict__ Dp) {
    __shared__ __align__(16) char sbuf[SC_RING * SC_CHB]; // 8 KB

    const int tid = threadIdx.x;
    const int b = blockIdx.x >> 5;
    const int diblk = blockIdx.x & 31;
    const int q = tid & 3;
    const int dil = tid >> 2;
    const int di = diblk * 32 + dil;
    const float LOG2E = 1.4426950408889634f;

    float A2[4];
#pragma unroll
    for (int j = 0; j < 4; j++) A2[j] = A_log[q * 4 + j] * LOG2E;
    const float Dv = Dp[di];
    const size_t rb = (size_t)b * SEQ;

    const int f_tl = tid >> 4;
    const int f_part = tid & 15;
    const int f_sub = f_part >> 2;
    const int f_off16 = (f_part & 3) * 8;
    auto fill = [&](int c) {
        size_t row = rb + (size_t)c * SC_CHUNK + f_tl;
        char* dst = sbuf + (c & (SC_RING - 1)) * SC_CHB + f_tl * SC_TB + f_sub * 64
                    + (f_part & 3) * 16;
        const bf16* src;
        if (f_sub == 0)      src = &g_dtbc[row * N2 + diblk * 32 + f_off16];
        else if (f_sub == 1) src = &g_xc[row * DI + diblk * 32 + f_off16];
        else if (f_sub == 2) src = &g_dtbc[row * N2 + 1024 + f_off16];
        else                 src = &g_xr[row * N1 + 1024 + diblk * 32 + f_off16];
        cp16(dst, src);
        cp_commit();
    };

    fill(0); fill(1); fill(2);

    float s0 = 0.f, s1 = 0.f, s2 = 0.f, s3 = 0.f;

#pragma unroll 1
    for (int c = 0; c < SC_NCH; c++) {
        asm volatile("cp.async.wait_group %0;\n" :: "n"(2));
        __syncthreads();                                  // single barrier per chunk
        const char* base = sbuf + (c & (SC_RING - 1)) * SC_CHB;
#pragma unroll
        for (int tl = 0; tl < SC_CHUNK; tl++) {
            const char* p = base + tl * SC_TB;
            float dt = bf2f(reinterpret_cast<const bf16*>(p)[dil]);
            float u  = bf2f(reinterpret_cast<const bf16*>(p + 64)[dil]);
            uint4 bc = *reinterpret_cast<const uint4*>(p + 128 + q * 16);
            float2 Bl = bf2x(bc.x), Bh = bf2x(bc.y);
            float2 Cl = bf2x(bc.z), Ch = bf2x(bc.w);
            float du = dt * u;

            float acc;
            s0 = fmaf(ex2f(dt * A2[0]), s0, du * Bl.x); acc = s0 * Cl.x;
            s1 = fmaf(ex2f(dt * A2[1]), s1, du * Bl.y); acc = fmaf(s1, Cl.y, acc);
            s2 = fmaf(ex2f(dt * A2[2]), s2, du * Bh.x); acc = fmaf(s2, Ch.x, acc);
            s3 = fmaf(ex2f(dt * A2[3]), s3, du * Bh.y); acc = fmaf(s3, Ch.y, acc);

            acc += __shfl_xor_sync(0xffffffffu, acc, 1);
            acc += __shfl_xor_sync(0xffffffffu, acc, 2);
            if (q == 0) {
                float rv = bf2f(reinterpret_cast<const bf16*>(p + 192)[dil]);
                float y = fmaf(u, Dv, acc);
                g_y2[(rb + (size_t)c * SC_CHUNK + tl) * DI + di] =
                    f2bf(y * rv * sigm(rv));
            }
        }
        // fill after compute; buffer (c+3)%4=(c-1)%4 free by top-barrier argument
        if (c + 3 < SC_NCH) fill(c + 3);
        else cp_commit();
    }
}

// ---------------- LayerNorm ----------------
__global__ void __launch_bounds__(256) k_ln(const float* __restrict__ gam,
                                            const float* __restrict__ bet,
                                            float* __restrict__ out) {
    int w = (blockIdx.x * 256 + threadIdx.x) >> 5;
    int lane = threadIdx.x & 31;
    if (w >= ROWS) return;
    const float* r = g_opre + (size_t)w * DM;
    float v[16], s = 0.f, ss = 0.f;
#pragma unroll
    for (int i = 0; i < 16; i++) {
        v[i] = r[i * 32 + lane];
        s += v[i];
        ss = fmaf(v[i], v[i], ss);
    }
#pragma unroll
    for (int o = 16; o; o >>= 1) {
        s += __shfl_xor_sync(0xffffffffu, s, o);
        ss += __shfl_xor_sync(0xffffffffu, ss, o);
    }
    float mu = s * (1.f / 512.f);
    float var = ss * (1.f / 512.f) - mu * mu;
    float rstd = rsqrtf(var + 1e-5f);
#pragma unroll
    for (int i = 0; i < 16; i++) {
        int c = i * 32 + lane;
        out[(size_t)w * DM + c] = (v[i] - mu) * rstd * gam[c] + bet[c];
    }
}

// ---------------- launch ----------------
extern "C" void kernel_launch(void* const* d_in, const int* in_sizes, int n_in,
                              void* d_out, int out_size) {
    const float* x      = (const float*)d_in[0];
    const float* W_in   = (const float*)d_in[1];
    const float* conv_w = (const float*)d_in[2];
    const float* conv_b = (const float*)d_in[3];
    const float* W_x    = (const float*)d_in[4];
    const float* W_dt   = (const float*)d_in[5];
    const float* b_dt   = (const float*)d_in[6];
    const float* A_log  = (const float*)d_in[7];
    const float* Dp     = (const float*)d_in[8];
    const float* W_out  = (const float*)d_in[9];
    const float* ln_g   = (const float*)d_in[10];
    const float* ln_b   = (const float*)d_in[11];
    float* out = (float*)d_out;

    static bool attr_done = false;
    if (!attr_done) {
        cudaFuncSetAttribute(k_gemm<1>, cudaFuncAttributeMaxDynamicSharedMemorySize, SMEM_TOT);
        cudaFuncSetAttribute(k_gemm<2>, cudaFuncAttributeMaxDynamicSharedMemorySize, SMEM_TOT);
        cudaFuncSetAttribute(k_gemm<3>, cudaFuncAttributeMaxDynamicSharedMemorySize, SMEM_TOT);
        attr_done = true;
    }

    // 1: prep
    k_prep<<<(PREP_TOT + 255) / 256, 256>>>(W_in, W_out, W_dt, W_x, b_dt, x);
    // 2: GEMM1 [32768,2048]
    k_gemm<1><<<dim3(N1 / 128, ROWS / 128), 256, SMEM_TOT>>>(nullptr);
    // 3: conv
    k_conv<<<ROWS * (DI / 4) / 256, 256>>>(conv_w, conv_b);
    // 4: GEMM2 [32768,1152]  <-- ncu capture window (verify STG=4 + 1-barrier)
    k_gemm<2><<<dim3(N2 / 128, ROWS / 128), 256, SMEM_TOT>>>(nullptr);
    // 5: scan (+ fused mulsilu) -> g_y2
    k_scan<<<B_SZ * 32, 128>>>(A_log, Dp);
    // 6: GEMM3 [32768,512] f32 + residual
    k_gemm<3><<<dim3(N3 / 128, ROWS / 128), 256, SMEM_TOT>>>(x);
    // 7: LN
    k_ln<<<(ROWS * 32 + 255) / 256, 256>>>(ln_g, ln_b, out);
}

// round 10
// speedup vs baseline: 2.5524x; 1.1601x over previous
#include <cuda_runtime.h>
#include <cuda_bf16.h>
#include <cstdint>

using bf16 = __nv_bfloat16;
using bf162 = __nv_bfloat162;

#define DEVFN __device__ __forceinline__

// ---------------- problem sizes ----------------
constexpr int B_SZ = 16, SEQ = 2048, DM = 512, DI = 1024, DS = 16;
constexpr int ROWS = B_SZ * SEQ;           // 32768
constexpr int N1 = 2 * DI;                 // 2048
constexpr int N2 = 1152;                   // 1024 dt + 32 (B|C natural) + 96 pad
constexpr int N3 = DM;                     // 512

// ---------------- scratch globals ----------------
__device__ __align__(256) bf16  g_xb  [(size_t)ROWS * DM];
__device__ __align__(256) bf16  g_W1  [(size_t)N1 * DM];
__device__ __align__(256) bf16  g_xr  [(size_t)ROWS * N1];   // x_p | silu-res
__device__ __align__(256) bf16  g_xc  [(size_t)ROWS * DI];
__device__ __align__(256) bf16  g_Wcat[(size_t)N2 * DI];
__device__ __align__(256) float g_b2  [N2];
__device__ __align__(256) bf16  g_dtbc[(size_t)ROWS * N2];
__device__ __align__(256) float g_bc  [(size_t)ROWS * 32];   // B|C f32 for scan
__device__ __align__(256) bf16  g_y2  [(size_t)ROWS * DI];
__device__ __align__(256) bf16  g_W3  [(size_t)N3 * DI];
__device__ __align__(256) float g_opre[(size_t)ROWS * DM];

// ---------------- helpers ----------------
DEVFN float bf2f(bf16 v) { return __bfloat162float(v); }
DEVFN bf16  f2bf(float v) { return __float2bfloat16(v); }
DEVFN uint32_t pack2(float a, float b) {
    bf162 t = __floats2bfloat162_rn(a, b);
    return *reinterpret_cast<uint32_t*>(&t);
}
DEVFN float2 bf2x(uint32_t u) { bf162 t = *reinterpret_cast<bf162*>(&u); return __bfloat1622float2(t); }
DEVFN float ex2f(float x) { float r; asm("ex2.approx.f32 %0, %1;" : "=f"(r) : "f"(x)); return r; }
DEVFN float clip10(float x) { return fminf(fmaxf(x, -10.f), 10.f); }
DEVFN float sigm(float x) { return 1.f / (1.f + __expf(-x)); }

DEVFN void cp16(void* s, const void* g) {
    unsigned sa = (unsigned)__cvta_generic_to_shared(s);
    asm volatile("cp.async.cg.shared.global [%0], [%1], 16;\n" :: "r"(sa), "l"(g));
}
DEVFN void cp_commit() { asm volatile("cp.async.commit_group;\n"); }
DEVFN void ldm4(uint32_t* r, const void* p) {
    unsigned a = (unsigned)__cvta_generic_to_shared(p);
    asm volatile("ldmatrix.sync.aligned.m8n8.x4.shared.b16 {%0,%1,%2,%3}, [%4];\n"
                 : "=r"(r[0]), "=r"(r[1]), "=r"(r[2]), "=r"(r[3]) : "r"(a));
}
DEVFN void mma16816(float* c, const uint32_t* a, const uint32_t* b) {
    asm volatile(
        "mma.sync.aligned.m16n8k16.row.col.f32.bf16.bf16.f32 "
        "{%0,%1,%2,%3}, {%4,%5,%6,%7}, {%8,%9}, {%0,%1,%2,%3};\n"
        : "+f"(c[0]), "+f"(c[1]), "+f"(c[2]), "+f"(c[3])
        : "r"(a[0]), "r"(a[1]), "r"(a[2]), "r"(a[3]), "r"(b[0]), "r"(b[1]));
}

// ---------------- merged prep kernel ----------------
constexpr int SG0 = N1 * DM;
constexpr int SG1 = N3 * DI;
constexpr int SG2 = N2 * DI;
constexpr int SG3 = N2;
constexpr int SG4 = ROWS * DM / 4;
constexpr int PREP_TOT = SG0 + SG1 + SG2 + SG3 + SG4;

__global__ void k_prep(const float* __restrict__ Win, const float* __restrict__ Wout,
                       const float* __restrict__ Wdt, const float* __restrict__ Wx,
                       const float* __restrict__ bdt, const float* __restrict__ x) {
    int i = blockIdx.x * 256 + threadIdx.x;
    if (i < SG0) { g_W1[i] = f2bf(Win[i]); return; }
    i -= SG0;
    if (i < SG1) { g_W3[i] = f2bf(Wout[i]); return; }
    i -= SG1;
    if (i < SG2) {
        int n = i / DI, k = i % DI;
        float v = 0.f;
        if (n < 1024)       v = Wdt[n * DI + k];
        else if (n < 1056)  v = Wx[(n - 1024) * DI + k];   // natural B | C order
        g_Wcat[i] = f2bf(v);
        return;
    }
    i -= SG2;
    if (i < SG3) { g_b2[i] = (i < 1024) ? bdt[i] : 0.f; return; }
    i -= SG3;
    if (i < SG4) {
        float4 v = *reinterpret_cast<const float4*>(x + (size_t)i * 4);
        uint2 pk;
        pk.x = pack2(clip10(v.x), clip10(v.y));
        pk.y = pack2(clip10(v.z), clip10(v.w));
        *reinterpret_cast<uint2*>(g_xb + (size_t)i * 4) = pk;
    }
}

// =====================================================================
// HMMA GEMM — CTA 128x128, 8 warps (4x2), warp 32x64, K-slab 32,
// STG=4 ring, single barrier per slab, exact commit accounting.
// SEL 1: epilogue applies silu to the res half (n>=1024).
// SEL 2: also stores BC columns (n in [1024,1056)) as f32 into g_bc.
// =====================================================================
constexpr int STG = 4;
constexpr int SCOLS = 40;
constexpr int A_STAGE = 128 * SCOLS;
constexpr int B_STAGE = 128 * SCOLS;
constexpr int SMEM_TOT = STG * (A_STAGE + B_STAGE) * 2;   // 81920 B

template <int SEL>
__global__ void __launch_bounds__(256, 2) k_gemm(const float* __restrict__ resid)
{
    constexpr int N = (SEL == 1) ? N1 : (SEL == 2) ? N2 : N3;
    constexpr int K = (SEL == 1) ? DM : DI;
    constexpr int KT = K / 32;
    const bf16* __restrict__ A  = (SEL == 1) ? g_xb : (SEL == 2) ? g_xc : g_y2;
    const bf16* __restrict__ Bw = (SEL == 1) ? g_W1 : (SEL == 2) ? g_Wcat : g_W3;

    extern __shared__ __align__(16) bf16 sm[];
    bf16* Asm = sm;
    bf16* Bsm = sm + STG * A_STAGE;

    const int tid = threadIdx.x, lane = tid & 31, warp = tid >> 5;
    const int wm = warp >> 1, wn = warp & 1;
    const int m0 = blockIdx.y * 128, n0 = blockIdx.x * 128;
    const bf16* Ap = A + (size_t)m0 * K;
    const bf16* Bp = Bw + (size_t)n0 * K;

    float acc[2][8][4];
#pragma unroll
    for (int i = 0; i < 2; i++)
#pragma unroll
        for (int j = 0; j < 8; j++)
#pragma unroll
            for (int v = 0; v < 4; v++) acc[i][j][v] = 0.f;

    auto fill = [&](int kt) {
        const int buf = kt % STG;
        bf16* As = Asm + buf * A_STAGE;
        bf16* Bs = Bsm + buf * B_STAGE;
#pragma unroll
        for (int i = 0; i < 2; i++) {
            int c = tid + i * 256;
            int row = c >> 2, col = (c & 3) << 3;
            cp16(As + row * SCOLS + col, Ap + (size_t)row * K + kt * 32 + col);
            cp16(Bs + row * SCOLS + col, Bp + (size_t)row * K + kt * 32 + col);
        }
        cp_commit();
    };

    fill(0); fill(1); fill(2);

#pragma unroll 1
    for (int kt = 0; kt < KT; kt++) {
        asm volatile("cp.async.wait_group %0;\n" :: "n"(2));
        __syncthreads();
        const int buf = kt % STG;
        const bf16* As = Asm + buf * A_STAGE;
        const bf16* Bs = Bsm + buf * B_STAGE;
#pragma unroll
        for (int kh = 0; kh < 2; kh++) {
            const int kk = kh * 16;
            uint32_t af[2][4], bfr[8][2];
#pragma unroll
            for (int mi = 0; mi < 2; mi++)
                ldm4(af[mi], As + (wm * 32 + mi * 16 + (lane & 15)) * SCOLS
                              + kk + ((lane >> 4) << 3));
#pragma unroll
            for (int ni2 = 0; ni2 < 4; ni2++) {
                uint32_t r[4];
                ldm4(r, Bs + (wn * 64 + ni2 * 16 + (lane & 15)) * SCOLS
                         + kk + ((lane >> 4) << 3));
                bfr[2 * ni2][0] = r[0]; bfr[2 * ni2][1] = r[2];
                bfr[2 * ni2 + 1][0] = r[1]; bfr[2 * ni2 + 1][1] = r[3];
            }
#pragma unroll
            for (int mi = 0; mi < 2; mi++)
#pragma unroll
                for (int ni = 0; ni < 8; ni++)
                    mma16816(acc[mi][ni], af[mi], bfr[ni]);
        }
        if (kt + 3 < KT) fill(kt + 3);
        else cp_commit();
    }

    // epilogue
    const bool resHalf = (SEL == 1) && (n0 >= 1024);      // uniform per CTA
#pragma unroll
    for (int mi = 0; mi < 2; mi++) {
#pragma unroll
        for (int ni = 0; ni < 8; ni++) {
            int mA = m0 + wm * 32 + mi * 16 + (lane >> 2);
            int n = n0 + wn * 64 + ni * 8 + ((lane & 3) << 1);
#pragma unroll
            for (int h = 0; h < 2; h++) {
                int mm = mA + h * 8;
                float v0 = acc[mi][ni][h * 2 + 0];
                float v1 = acc[mi][ni][h * 2 + 1];
                size_t idx = (size_t)mm * N + n;
                if (SEL == 1) {
                    if (resHalf) { v0 *= sigm(v0); v1 *= sigm(v1); }   // pre-silu res
                    *reinterpret_cast<bf162*>(g_xr + idx) = __floats2bfloat162_rn(v0, v1);
                } else if (SEL == 2) {
                    v0 += g_b2[n]; v1 += g_b2[n + 1];
                    *reinterpret_cast<bf162*>(g_dtbc + idx) = __floats2bfloat162_rn(v0, v1);
                    if (n >= 1024 && n < 1056)
                        *reinterpret_cast<float2*>(&g_bc[(size_t)mm * 32 + (n - 1024)]) =
                            make_float2(v0, v1);
                } else {
                    float x0 = clip10(resid[idx]);
                    float x1 = clip10(resid[idx + 1]);
                    *reinterpret_cast<float2*>(g_opre + idx) = make_float2(v0 + x0, v1 + x1);
                }
            }
        }
    }
}

// ---------------- causal depthwise conv(4) + SiLU, 4 di / thread --------
__global__ void k_conv(const float* __restrict__ cw, const float* __restrict__ cb) {
    int idx = blockIdx.x * 256 + threadIdx.x;
    if (idx >= ROWS * (DI / 4)) return;
    int di4 = (idx & 255) * 4;
    size_t row = (size_t)(idx >> 8);
    int t = (int)(row % SEQ);

    float acc[4] = { cb[di4], cb[di4 + 1], cb[di4 + 2], cb[di4 + 3] };
    float4 w0 = *reinterpret_cast<const float4*>(cw + (di4 + 0) * 4);
    float4 w1 = *reinterpret_cast<const float4*>(cw + (di4 + 1) * 4);
    float4 w2 = *reinterpret_cast<const float4*>(cw + (di4 + 2) * 4);
    float4 w3 = *reinterpret_cast<const float4*>(cw + (di4 + 3) * 4);
    const float* wv[4] = { (const float*)&w0, (const float*)&w1,
                           (const float*)&w2, (const float*)&w3 };
#pragma unroll
    for (int k = 0; k < 4; k++) {
        if (t - 3 + k < 0) continue;
        uint2 raw = *reinterpret_cast<const uint2*>(&g_xr[(row - 3 + k) * N1 + di4]);
        float2 lo = bf2x(raw.x), hi = bf2x(raw.y);
        acc[0] = fmaf(wv[0][k], lo.x, acc[0]);
        acc[1] = fmaf(wv[1][k], lo.y, acc[1]);
        acc[2] = fmaf(wv[2][k], hi.x, acc[2]);
        acc[3] = fmaf(wv[3][k], hi.y, acc[3]);
    }
#pragma unroll
    for (int j = 0; j < 4; j++) acc[j] = acc[j] * sigm(acc[j]);
    uint2 pk;
    pk.x = pack2(acc[0], acc[1]);
    pk.y = pack2(acc[2], acc[3]);
    *reinterpret_cast<uint2*>(&g_xc[row * DI + di4]) = pk;
}

// =====================================================================
// Selective scan: 64-thread blocks (16 di x 4 q), 1024 blocks,
// cp.async ring, f32 B/C (no unpack), pre-silu'ed res, fused output.
// Per t in smem (224B): dt 32B | u 32B | B 64B f32 | C 64B f32 | res 32B
// =====================================================================
constexpr int SC_CHUNK = 8;
constexpr int SC_RING = 4;
constexpr int SC_TB = 224;
constexpr int SC_CHB = SC_CHUNK * SC_TB;                  // 1792 B
constexpr int SC_NCH = SEQ / SC_CHUNK;                    // 256

__global__ void __launch_bounds__(64) k_scan(const float* __restrict__ A_log,
                                             const float* __restrict__ Dp) {
    __shared__ __align__(16) char sbuf[SC_RING * SC_CHB]; // 7168 B

    const int tid = threadIdx.x;
    const int b = blockIdx.x >> 6;
    const int diblk = blockIdx.x & 63;                    // 64 blocks of 16 di
    const int q = tid & 3;
    const int dil = tid >> 2;                             // 0..15
    const int di = diblk * 16 + dil;
    const float LOG2E = 1.4426950408889634f;

    float A2[4];
#pragma unroll
    for (int j = 0; j < 4; j++) A2[j] = A_log[q * 4 + j] * LOG2E;
    const float Dv = Dp[di];
    const size_t rb = (size_t)b * SEQ;

    auto fill = [&](int c) {
#pragma unroll
        for (int r = 0; r < 2; r++) {
            int cc = tid + r * 64;
            if (cc < 112) {                               // 14 cp16 per t x 8 t
                int t = cc / 14, part = cc % 14;
                size_t row = rb + (size_t)c * SC_CHUNK + t;
                char* dst = sbuf + (c & (SC_RING - 1)) * SC_CHB + t * SC_TB;
                const char* src;
                if (part < 2) {
                    dst += part * 16;
                    src = (const char*)&g_dtbc[row * N2 + diblk * 16] + part * 16;
                } else if (part < 4) {
                    dst += 32 + (part - 2) * 16;
                    src = (const char*)&g_xc[row * DI + diblk * 16] + (part - 2) * 16;
                } else if (part < 12) {
                    dst += 64 + (part - 4) * 16;
                    src = (const char*)&g_bc[row * 32] + (part - 4) * 16;
                } else {
                    dst += 192 + (part - 12) * 16;
                    src = (const char*)&g_xr[row * N1 + 1024 + diblk * 16] + (part - 12) * 16;
                }
                cp16(dst, src);
            }
        }
        cp_commit();
    };

    fill(0); fill(1); fill(2);

    float s0 = 0.f, s1 = 0.f, s2 = 0.f, s3 = 0.f;

#pragma unroll 1
    for (int c = 0; c < SC_NCH; c++) {
        asm volatile("cp.async.wait_group %0;\n" :: "n"(2));
        __syncthreads();
        const char* base = sbuf + (c & (SC_RING - 1)) * SC_CHB;
#pragma unroll
        for (int tl = 0; tl < SC_CHUNK; tl++) {
            const char* p = base + tl * SC_TB;
            float dt = bf2f(reinterpret_cast<const bf16*>(p)[dil]);
            float u  = bf2f(reinterpret_cast<const bf16*>(p + 32)[dil]);
            float4 B4 = *reinterpret_cast<const float4*>(p + 64 + q * 16);
            float4 C4 = *reinterpret_cast<const float4*>(p + 128 + q * 16);
            float du = dt * u;

            float acc;
            s0 = fmaf(ex2f(dt * A2[0]), s0, du * B4.x); acc = s0 * C4.x;
            s1 = fmaf(ex2f(dt * A2[1]), s1, du * B4.y); acc = fmaf(s1, C4.y, acc);
            s2 = fmaf(ex2f(dt * A2[2]), s2, du * B4.z); acc = fmaf(s2, C4.z, acc);
            s3 = fmaf(ex2f(dt * A2[3]), s3, du * B4.w); acc = fmaf(s3, C4.w, acc);

            acc += __shfl_xor_sync(0xffffffffu, acc, 1);
            acc += __shfl_xor_sync(0xffffffffu, acc, 2);
            if (q == 0) {
                float rp = bf2f(reinterpret_cast<const bf16*>(p + 192)[dil]);  // pre-silu'ed
                g_y2[(rb + (size_t)c * SC_CHUNK + tl) * DI + di] =
                    f2bf(fmaf(u, Dv, acc) * rp);
            }
        }
        if (c + 3 < SC_NCH) fill(c + 3);
        else cp_commit();
    }
}

// ---------------- LayerNorm ----------------
__global__ void __launch_bounds__(256) k_ln(const float* __restrict__ gam,
                                            const float* __restrict__ bet,
                                            float* __restrict__ out) {
    int w = (blockIdx.x * 256 + threadIdx.x) >> 5;
    int lane = threadIdx.x & 31;
    if (w >= ROWS) return;
    const float* r = g_opre + (size_t)w * DM;
    float v[16], s = 0.f, ss = 0.f;
#pragma unroll
    for (int i = 0; i < 16; i++) {
        v[i] = r[i * 32 + lane];
        s += v[i];
        ss = fmaf(v[i], v[i], ss);
    }
#pragma unroll
    for (int o = 16; o; o >>= 1) {
        s += __shfl_xor_sync(0xffffffffu, s, o);
        ss += __shfl_xor_sync(0xffffffffu, ss, o);
    }
    float mu = s * (1.f / 512.f);
    float var = ss * (1.f / 512.f) - mu * mu;
    float rstd = rsqrtf(var + 1e-5f);
#pragma unroll
    for (int i = 0; i < 16; i++) {
        int c = i * 32 + lane;
        out[(size_t)w * DM + c] = (v[i] - mu) * rstd * gam[c] + bet[c];
    }
}

// ---------------- launch ----------------
extern "C" void kernel_launch(void* const* d_in, const int* in_sizes, int n_in,
                              void* d_out, int out_size) {
    const float* x      = (const float*)d_in[0];
    const float* W_in   = (const float*)d_in[1];
    const float* conv_w = (const float*)d_in[2];
    const float* conv_b = (const float*)d_in[3];
    const float* W_x    = (const float*)d_in[4];
    const float* W_dt   = (const float*)d_in[5];
    const float* b_dt   = (const float*)d_in[6];
    const float* A_log  = (const float*)d_in[7];
    const float* Dp     = (const float*)d_in[8];
    const float* W_out  = (const float*)d_in[9];
    const float* ln_g   = (const float*)d_in[10];
    const float* ln_b   = (const float*)d_in[11];
    float* out = (float*)d_out;

    static bool attr_done = false;
    if (!attr_done) {
        cudaFuncSetAttribute(k_gemm<1>, cudaFuncAttributeMaxDynamicSharedMemorySize, SMEM_TOT);
        cudaFuncSetAttribute(k_gemm<2>, cudaFuncAttributeMaxDynamicSharedMemorySize, SMEM_TOT);
        cudaFuncSetAttribute(k_gemm<3>, cudaFuncAttributeMaxDynamicSharedMemorySize, SMEM_TOT);
        attr_done = true;
    }

    // 1: prep
    k_prep<<<(PREP_TOT + 255) / 256, 256>>>(W_in, W_out, W_dt, W_x, b_dt, x);
    // 2: GEMM1 [32768,2048] (res half pre-silu'ed)
    k_gemm<1><<<dim3(N1 / 128, ROWS / 128), 256, SMEM_TOT>>>(nullptr);
    // 3: conv
    k_conv<<<ROWS * (DI / 4) / 256, 256>>>(conv_w, conv_b);
    // 4: GEMM2 [32768,1152] (+f32 BC side-store)  <-- ncu capture window
    k_gemm<2><<<dim3(N2 / 128, ROWS / 128), 256, SMEM_TOT>>>(nullptr);
    // 5: scan (+ fused mulsilu) -> g_y2
    k_scan<<<B_SZ * 64, 64>>>(A_log, Dp);
    // 6: GEMM3 [32768,512] f32 + residual
    k_gemm<3><<<dim3(N3 / 128, ROWS / 128), 256, SMEM_TOT>>>(x);
    // 7: LN
    k_ln<<<(ROWS * 32 + 255) / 256, 256>>>(ln_g, ln_b, out);
}

// round 11
// speedup vs baseline: 2.7893x; 1.0928x over previous
#include <cuda_runtime.h>
#include <cuda_fp16.h>
#include <cstdint>

using fp16 = __half;
using h2 = __half2;

#define DEVFN __device__ __forceinline__

// ---------------- problem sizes ----------------
constexpr int B_SZ = 16, SEQ = 2048, DM = 512, DI = 1024, DS = 16;
constexpr int ROWS = B_SZ * SEQ;           // 32768
constexpr int N1 = 2 * DI;                 // 2048
constexpr int N2 = 1152;                   // 1024 dt + 32 (B|C) + 96 pad
constexpr int N3 = DM;                     // 512

// ---------------- scratch globals (fp16 intermediates) ----------------
__device__ __align__(256) fp16  g_xb  [(size_t)ROWS * DM];
__device__ __align__(256) fp16  g_W1  [(size_t)N1 * DM];
__device__ __align__(256) fp16  g_xr  [(size_t)ROWS * N1];   // x_p | silu(res)
__device__ __align__(256) fp16  g_xc  [(size_t)ROWS * DI];
__device__ __align__(256) fp16  g_Wcat[(size_t)N2 * DI];
__device__ __align__(256) float g_b2  [N2];
__device__ __align__(256) fp16  g_dtbc[(size_t)ROWS * N2];
__device__ __align__(256) float g_bc  [(size_t)ROWS * 32];   // B|C f32 for scan
__device__ __align__(256) fp16  g_y2  [(size_t)ROWS * DI];
__device__ __align__(256) fp16  g_W3  [(size_t)N3 * DI];
__device__ __align__(256) float g_opre[(size_t)ROWS * DM];

// ---------------- helpers ----------------
DEVFN float h2f(fp16 v) { return __half2float(v); }
DEVFN fp16  f2h(float v) { return __float2half(v); }
DEVFN float2 h2x(uint32_t u) { h2 t = *reinterpret_cast<h2*>(&u); return __half22float2(t); }
DEVFN uint32_t pack2h(float a, float b) {
    h2 t = __floats2half2_rn(a, b);
    return *reinterpret_cast<uint32_t*>(&t);
}
DEVFN float ex2f(float x) { float r; asm("ex2.approx.f32 %0, %1;" : "=f"(r) : "f"(x)); return r; }
DEVFN float clip10(float x) { return fminf(fmaxf(x, -10.f), 10.f); }
DEVFN float sigm(float x) { return 1.f / (1.f + __expf(-x)); }

DEVFN void cp16(void* s, const void* g) {
    unsigned sa = (unsigned)__cvta_generic_to_shared(s);
    asm volatile("cp.async.cg.shared.global [%0], [%1], 16;\n" :: "r"(sa), "l"(g));
}
DEVFN void cp_commit() { asm volatile("cp.async.commit_group;\n"); }
DEVFN void ldm4(uint32_t* r, const void* p) {
    unsigned a = (unsigned)__cvta_generic_to_shared(p);
    asm volatile("ldmatrix.sync.aligned.m8n8.x4.shared.b16 {%0,%1,%2,%3}, [%4];\n"
                 : "=r"(r[0]), "=r"(r[1]), "=r"(r[2]), "=r"(r[3]) : "r"(a));
}
// fp16 inputs, fp16 accumulators (2 regs)
DEVFN void mma_h(uint32_t* c, const uint32_t* a, const uint32_t* b) {
    asm volatile(
        "mma.sync.aligned.m16n8k16.row.col.f16.f16.f16.f16 "
        "{%0,%1}, {%2,%3,%4,%5}, {%6,%7}, {%0,%1};\n"
        : "+r"(c[0]), "+r"(c[1])
        : "r"(a[0]), "r"(a[1]), "r"(a[2]), "r"(a[3]), "r"(b[0]), "r"(b[1]));
}
// fp16 inputs, f32 accumulators (4 regs)
DEVFN void mma_f(float* c, const uint32_t* a, const uint32_t* b) {
    asm volatile(
        "mma.sync.aligned.m16n8k16.row.col.f32.f16.f16.f32 "
        "{%0,%1,%2,%3}, {%4,%5,%6,%7}, {%8,%9}, {%0,%1,%2,%3};\n"
        : "+f"(c[0]), "+f"(c[1]), "+f"(c[2]), "+f"(c[3])
        : "r"(a[0]), "r"(a[1]), "r"(a[2]), "r"(a[3]), "r"(b[0]), "r"(b[1]));
}

// ---------------- merged prep kernel ----------------
constexpr int SG0 = N1 * DM;
constexpr int SG1 = N3 * DI;
constexpr int SG2 = N2 * DI;
constexpr int SG3 = N2;
constexpr int SG4 = ROWS * DM / 4;
constexpr int PREP_TOT = SG0 + SG1 + SG2 + SG3 + SG4;

__global__ void k_prep(const float* __restrict__ Win, const float* __restrict__ Wout,
                       const float* __restrict__ Wdt, const float* __restrict__ Wx,
                       const float* __restrict__ bdt, const float* __restrict__ x) {
    int i = blockIdx.x * 256 + threadIdx.x;
    if (i < SG0) { g_W1[i] = f2h(Win[i]); return; }
    i -= SG0;
    if (i < SG1) { g_W3[i] = f2h(Wout[i]); return; }
    i -= SG1;
    if (i < SG2) {
        int n = i / DI, k = i % DI;
        float v = 0.f;
        if (n < 1024)       v = Wdt[n * DI + k];
        else if (n < 1056)  v = Wx[(n - 1024) * DI + k];   // natural B | C order
        g_Wcat[i] = f2h(v);
        return;
    }
    i -= SG2;
    if (i < SG3) { g_b2[i] = (i < 1024) ? bdt[i] : 0.f; return; }
    i -= SG3;
    if (i < SG4) {
        float4 v = *reinterpret_cast<const float4*>(x + (size_t)i * 4);
        uint2 pk;
        pk.x = pack2h(clip10(v.x), clip10(v.y));
        pk.y = pack2h(clip10(v.z), clip10(v.w));
        *reinterpret_cast<uint2*>(g_xb + (size_t)i * 4) = pk;
    }
}

// =====================================================================
// HMMA GEMM — CTA 128x128, 8 warps (4x2), warp 32x64, K-slab 32.
// SEL 1/2: fp16 accumulators, STG=3, 3 CTAs/SM.
// SEL 3  : f32 accumulators,  STG=4, 2 CTAs/SM.
// Single barrier per slab; fill-after-compute; exact commit accounting.
// =====================================================================
constexpr int SCOLS = 40;
constexpr int A_STAGE = 128 * SCOLS;   // elements per stage per operand
constexpr int B_STAGE = 128 * SCOLS;
constexpr int SMEM_12 = 3 * (A_STAGE + B_STAGE) * 2;   // 61440 B
constexpr int SMEM_3  = 4 * (A_STAGE + B_STAGE) * 2;   // 81920 B

template <int SEL>
__global__ void __launch_bounds__(256, (SEL == 3) ? 2 : 3)
k_gemm(const float* __restrict__ resid)
{
    constexpr int N = (SEL == 1) ? N1 : (SEL == 2) ? N2 : N3;
    constexpr int K = (SEL == 1) ? DM : DI;
    constexpr int KT = K / 32;
    constexpr int STG_K = (SEL == 3) ? 4 : 3;
    const fp16* __restrict__ A  = (SEL == 1) ? g_xb : (SEL == 2) ? g_xc : g_y2;
    const fp16* __restrict__ Bw = (SEL == 1) ? g_W1 : (SEL == 2) ? g_Wcat : g_W3;

    extern __shared__ __align__(16) fp16 sm[];
    fp16* Asm = sm;
    fp16* Bsm = sm + STG_K * A_STAGE;

    const int tid = threadIdx.x, lane = tid & 31, warp = tid >> 5;
    const int wm = warp >> 1, wn = warp & 1;
    const int m0 = blockIdx.y * 128, n0 = blockIdx.x * 128;
    const fp16* Ap = A + (size_t)m0 * K;
    const fp16* Bp = Bw + (size_t)n0 * K;

    uint32_t acch[2][8][2];
    float    accf[2][8][4];
    if constexpr (SEL == 3) {
#pragma unroll
        for (int i = 0; i < 2; i++)
#pragma unroll
            for (int j = 0; j < 8; j++)
#pragma unroll
                for (int v = 0; v < 4; v++) accf[i][j][v] = 0.f;
    } else {
#pragma unroll
        for (int i = 0; i < 2; i++)
#pragma unroll
            for (int j = 0; j < 8; j++) { acch[i][j][0] = 0u; acch[i][j][1] = 0u; }
    }

    auto fill = [&](int kt) {
        const int buf = kt % STG_K;
        fp16* As = Asm + buf * A_STAGE;
        fp16* Bs = Bsm + buf * B_STAGE;
#pragma unroll
        for (int i = 0; i < 2; i++) {
            int c = tid + i * 256;
            int row = c >> 2, col = (c & 3) << 3;
            cp16(As + row * SCOLS + col, Ap + (size_t)row * K + kt * 32 + col);
            cp16(Bs + row * SCOLS + col, Bp + (size_t)row * K + kt * 32 + col);
        }
        cp_commit();
    };

#pragma unroll
    for (int p = 0; p < STG_K - 1; p++) fill(p);

#pragma unroll 1
    for (int kt = 0; kt < KT; kt++) {
        if constexpr (STG_K == 3) asm volatile("cp.async.wait_group 1;\n");
        else                      asm volatile("cp.async.wait_group 2;\n");
        __syncthreads();                                 // single barrier per slab
        const int buf = kt % STG_K;
        const fp16* As = Asm + buf * A_STAGE;
        const fp16* Bs = Bsm + buf * B_STAGE;
#pragma unroll
        for (int kh = 0; kh < 2; kh++) {
            const int kk = kh * 16;
            uint32_t af[2][4], bfr[8][2];
#pragma unroll
            for (int mi = 0; mi < 2; mi++)
                ldm4(af[mi], As + (wm * 32 + mi * 16 + (lane & 15)) * SCOLS
                              + kk + ((lane >> 4) << 3));
#pragma unroll
            for (int ni2 = 0; ni2 < 4; ni2++) {
                uint32_t r[4];
                ldm4(r, Bs + (wn * 64 + ni2 * 16 + (lane & 15)) * SCOLS
                         + kk + ((lane >> 4) << 3));
                bfr[2 * ni2][0] = r[0]; bfr[2 * ni2][1] = r[2];
                bfr[2 * ni2 + 1][0] = r[1]; bfr[2 * ni2 + 1][1] = r[3];
            }
#pragma unroll
            for (int mi = 0; mi < 2; mi++)
#pragma unroll
                for (int ni = 0; ni < 8; ni++) {
                    if constexpr (SEL == 3) mma_f(accf[mi][ni], af[mi], bfr[ni]);
                    else                    mma_h(acch[mi][ni], af[mi], bfr[ni]);
                }
        }
        // fill after compute; target buf (kt-1)%STG_K is free (top barrier argument)
        if (kt + STG_K - 1 < KT) fill(kt + STG_K - 1);
        else cp_commit();
    }

    // epilogue
    const bool resHalf = (SEL == 1) && (n0 >= 1024);      // uniform per CTA
#pragma unroll
    for (int mi = 0; mi < 2; mi++) {
#pragma unroll
        for (int ni = 0; ni < 8; ni++) {
            int mA = m0 + wm * 32 + mi * 16 + (lane >> 2);
            int n = n0 + wn * 64 + ni * 8 + ((lane & 3) << 1);
#pragma unroll
            for (int h = 0; h < 2; h++) {
                int mm = mA + h * 8;
                size_t idx = (size_t)mm * N + n;
                float v0, v1;
                if constexpr (SEL == 3) {
                    v0 = accf[mi][ni][h * 2 + 0];
                    v1 = accf[mi][ni][h * 2 + 1];
                } else {
                    float2 t = h2x(acch[mi][ni][h]);
                    v0 = t.x; v1 = t.y;
                }
                if (SEL == 1) {
                    if (resHalf) { v0 *= sigm(v0); v1 *= sigm(v1); }   // pre-silu res
                    *reinterpret_cast<uint32_t*>(g_xr + idx) = pack2h(v0, v1);
                } else if (SEL == 2) {
                    v0 += g_b2[n]; v1 += g_b2[n + 1];
                    *reinterpret_cast<uint32_t*>(g_dtbc + idx) = pack2h(v0, v1);
                    if (n >= 1024 && n < 1056)
                        *reinterpret_cast<float2*>(&g_bc[(size_t)mm * 32 + (n - 1024)]) =
                            make_float2(v0, v1);
                } else {
                    float x0 = clip10(resid[idx]);
                    float x1 = clip10(resid[idx + 1]);
                    *reinterpret_cast<float2*>(g_opre + idx) = make_float2(v0 + x0, v1 + x1);
                }
            }
        }
    }
}

// ---------------- causal depthwise conv(4) + SiLU, 4 di / thread --------
__global__ void k_conv(const float* __restrict__ cw, const float* __restrict__ cb) {
    int idx = blockIdx.x * 256 + threadIdx.x;
    if (idx >= ROWS * (DI / 4)) return;
    int di4 = (idx & 255) * 4;
    size_t row = (size_t)(idx >> 8);
    int t = (int)(row % SEQ);

    float acc[4] = { cb[di4], cb[di4 + 1], cb[di4 + 2], cb[di4 + 3] };
    float4 w0 = *reinterpret_cast<const float4*>(cw + (di4 + 0) * 4);
    float4 w1 = *reinterpret_cast<const float4*>(cw + (di4 + 1) * 4);
    float4 w2 = *reinterpret_cast<const float4*>(cw + (di4 + 2) * 4);
    float4 w3 = *reinterpret_cast<const float4*>(cw + (di4 + 3) * 4);
    const float* wv[4] = { (const float*)&w0, (const float*)&w1,
                           (const float*)&w2, (const float*)&w3 };
#pragma unroll
    for (int k = 0; k < 4; k++) {
        if (t - 3 + k < 0) continue;
        uint2 raw = *reinterpret_cast<const uint2*>(&g_xr[(row - 3 + k) * N1 + di4]);
        float2 lo = h2x(raw.x), hi = h2x(raw.y);
        acc[0] = fmaf(wv[0][k], lo.x, acc[0]);
        acc[1] = fmaf(wv[1][k], lo.y, acc[1]);
        acc[2] = fmaf(wv[2][k], hi.x, acc[2]);
        acc[3] = fmaf(wv[3][k], hi.y, acc[3]);
    }
#pragma unroll
    for (int j = 0; j < 4; j++) acc[j] = acc[j] * sigm(acc[j]);
    uint2 pk;
    pk.x = pack2h(acc[0], acc[1]);
    pk.y = pack2h(acc[2], acc[3]);
    *reinterpret_cast<uint2*>(&g_xc[row * DI + di4]) = pk;
}

// =====================================================================
// Selective scan: 64-thread blocks (16 di x 4 q), 1024 blocks,
// cp.async ring, f32 B/C, pre-silu'ed res, fused output.
// Chunk = 16 t (halved barrier count vs R10).
// Per t in smem (224B): dt 32B | u 32B | B 64B f32 | C 64B f32 | res 32B
// =====================================================================
constexpr int SC_CHUNK = 16;
constexpr int SC_RING = 4;
constexpr int SC_TB = 224;
constexpr int SC_CHB = SC_CHUNK * SC_TB;                  // 3584 B
constexpr int SC_NCH = SEQ / SC_CHUNK;                    // 128

__global__ void __launch_bounds__(64) k_scan(const float* __restrict__ A_log,
                                             const float* __restrict__ Dp) {
    __shared__ __align__(16) char sbuf[SC_RING * SC_CHB]; // 14336 B

    const int tid = threadIdx.x;
    const int b = blockIdx.x >> 6;
    const int diblk = blockIdx.x & 63;
    const int q = tid & 3;
    const int dil = tid >> 2;                             // 0..15
    const int di = diblk * 16 + dil;
    const float LOG2E = 1.4426950408889634f;

    float A2[4];
#pragma unroll
    for (int j = 0; j < 4; j++) A2[j] = A_log[q * 4 + j] * LOG2E;
    const float Dv = Dp[di];
    const size_t rb = (size_t)b * SEQ;

    auto fill = [&](int c) {
#pragma unroll
        for (int r = 0; r < 4; r++) {
            int cc = tid + r * 64;                        // 0..255
            if (cc < 14 * SC_CHUNK) {                     // 14 cp16 per t
                int t = cc / 14, part = cc % 14;
                size_t row = rb + (size_t)c * SC_CHUNK + t;
                char* dst = sbuf + (c & (SC_RING - 1)) * SC_CHB + t * SC_TB;
                const char* src;
                if (part < 2) {
                    dst += part * 16;
                    src = (const char*)&g_dtbc[row * N2 + diblk * 16] + part * 16;
                } else if (part < 4) {
                    dst += 32 + (part - 2) * 16;
                    src = (const char*)&g_xc[row * DI + diblk * 16] + (part - 2) * 16;
                } else if (part < 12) {
                    dst += 64 + (part - 4) * 16;
                    src = (const char*)&g_bc[row * 32] + (part - 4) * 16;
                } else {
                    dst += 192 + (part - 12) * 16;
                    src = (const char*)&g_xr[row * N1 + 1024 + diblk * 16] + (part - 12) * 16;
                }
                cp16(dst, src);
            }
        }
        cp_commit();
    };

    fill(0); fill(1); fill(2);

    float s0 = 0.f, s1 = 0.f, s2 = 0.f, s3 = 0.f;

#pragma unroll 1
    for (int c = 0; c < SC_NCH; c++) {
        asm volatile("cp.async.wait_group %0;\n" :: "n"(2));
        __syncthreads();
        const char* base = sbuf + (c & (SC_RING - 1)) * SC_CHB;
#pragma unroll
        for (int tl = 0; tl < SC_CHUNK; tl++) {
            const char* p = base + tl * SC_TB;
            float dt = h2f(reinterpret_cast<const fp16*>(p)[dil]);
            float u  = h2f(reinterpret_cast<const fp16*>(p + 32)[dil]);
            float4 B4 = *reinterpret_cast<const float4*>(p + 64 + q * 16);
            float4 C4 = *reinterpret_cast<const float4*>(p + 128 + q * 16);
            float du = dt * u;

            float acc;
            s0 = fmaf(ex2f(dt * A2[0]), s0, du * B4.x); acc = s0 * C4.x;
            s1 = fmaf(ex2f(dt * A2[1]), s1, du * B4.y); acc = fmaf(s1, C4.y, acc);
            s2 = fmaf(ex2f(dt * A2[2]), s2, du * B4.z); acc = fmaf(s2, C4.z, acc);
            s3 = fmaf(ex2f(dt * A2[3]), s3, du * B4.w); acc = fmaf(s3, C4.w, acc);

            acc += __shfl_xor_sync(0xffffffffu, acc, 1);
            acc += __shfl_xor_sync(0xffffffffu, acc, 2);
            if (q == 0) {
                float rp = h2f(reinterpret_cast<const fp16*>(p + 192)[dil]);  // pre-silu'ed
                g_y2[(rb + (size_t)c * SC_CHUNK + tl) * DI + di] =
                    f2h(fmaf(u, Dv, acc) * rp);
            }
        }
        if (c + 3 < SC_NCH) fill(c + 3);
        else cp_commit();
    }
}

// ---------------- LayerNorm ----------------
__global__ void __launch_bounds__(256) k_ln(const float* __restrict__ gam,
                                            const float* __restrict__ bet,
                                            float* __restrict__ out) {
    int w = (blockIdx.x * 256 + threadIdx.x) >> 5;
    int lane = threadIdx.x & 31;
    if (w >= ROWS) return;
    const float* r = g_opre + (size_t)w * DM;
    float v[16], s = 0.f, ss = 0.f;
#pragma unroll
    for (int i = 0; i < 16; i++) {
        v[i] = r[i * 32 + lane];
        s += v[i];
        ss = fmaf(v[i], v[i], ss);
    }
#pragma unroll
    for (int o = 16; o; o >>= 1) {
        s += __shfl_xor_sync(0xffffffffu, s, o);
        ss += __shfl_xor_sync(0xffffffffu, ss, o);
    }
    float mu = s * (1.f / 512.f);
    float var = ss * (1.f / 512.f) - mu * mu;
    float rstd = rsqrtf(var + 1e-5f);
#pragma unroll
    for (int i = 0; i < 16; i++) {
        int c = i * 32 + lane;
        out[(size_t)w * DM + c] = (v[i] - mu) * rstd * gam[c] + bet[c];
    }
}

// ---------------- launch ----------------
extern "C" void kernel_launch(void* const* d_in, const int* in_sizes, int n_in,
                              void* d_out, int out_size) {
    const float* x      = (const float*)d_in[0];
    const float* W_in   = (const float*)d_in[1];
    const float* conv_w = (const float*)d_in[2];
    const float* conv_b = (const float*)d_in[3];
    const float* W_x    = (const float*)d_in[4];
    const float* W_dt   = (const float*)d_in[5];
    const float* b_dt   = (const float*)d_in[6];
    const float* A_log  = (const float*)d_in[7];
    const float* Dp     = (const float*)d_in[8];
    const float* W_out  = (const float*)d_in[9];
    const float* ln_g   = (const float*)d_in[10];
    const float* ln_b   = (const float*)d_in[11];
    float* out = (float*)d_out;

    static bool attr_done = false;
    if (!attr_done) {
        cudaFuncSetAttribute(k_gemm<1>, cudaFuncAttributeMaxDynamicSharedMemorySize, SMEM_12);
        cudaFuncSetAttribute(k_gemm<2>, cudaFuncAttributeMaxDynamicSharedMemorySize, SMEM_12);
        cudaFuncSetAttribute(k_gemm<3>, cudaFuncAttributeMaxDynamicSharedMemorySize, SMEM_3);
        attr_done = true;
    }

    // 1: prep
    k_prep<<<(PREP_TOT + 255) / 256, 256>>>(W_in, W_out, W_dt, W_x, b_dt, x);
    // 2: GEMM1 [32768,2048] fp16-acc (res half pre-silu'ed)
    k_gemm<1><<<dim3(N1 / 128, ROWS / 128), 256, SMEM_12>>>(nullptr);
    // 3: conv
    k_conv<<<ROWS * (DI / 4) / 256, 256>>>(conv_w, conv_b);
    // 4: GEMM2 [32768,1152] fp16-acc (+f32 BC side-store)  <-- ncu window
    k_gemm<2><<<dim3(N2 / 128, ROWS / 128), 256, SMEM_12>>>(nullptr);
    // 5: scan (+ fused mulsilu) -> g_y2
    k_scan<<<B_SZ * 64, 64>>>(A_log, Dp);
    // 6: GEMM3 [32768,512] f32-acc + residual
    k_gemm<3><<<dim3(N3 / 128, ROWS / 128), 256, SMEM_3>>>(x);
    // 7: LN
    k_ln<<<(ROWS * 32 + 255) / 256, 256>>>(ln_g, ln_b, out);
}

// round 13
// speedup vs baseline: 2.8008x; 1.0041x over previous
#include <cuda_runtime.h>
#include <cuda_fp16.h>
#include <cstdint>

using fp16 = __half;
using h2 = __half2;

#define DEVFN __device__ __forceinline__

// ---------------- problem sizes ----------------
constexpr int B_SZ = 16, SEQ = 2048, DM = 512, DI = 1024, DS = 16;
constexpr int ROWS = B_SZ * SEQ;           // 32768
constexpr int N1 = 2 * DI;                 // 2048
constexpr int N2 = 1152;                   // 1024 dt + 32 (B|C) + 96 pad
constexpr int N3 = DM;                     // 512

// ---------------- scratch globals (fp16 intermediates) ----------------
__device__ __align__(256) fp16  g_xb  [(size_t)ROWS * DM];
__device__ __align__(256) fp16  g_W1  [(size_t)N1 * DM];
__device__ __align__(256) fp16  g_xr  [(size_t)ROWS * N1];   // x_p | silu(res)
__device__ __align__(256) fp16  g_xc  [(size_t)ROWS * DI];
__device__ __align__(256) fp16  g_Wcat[(size_t)N2 * DI];
__device__ __align__(256) float g_b2  [N2];
__device__ __align__(256) fp16  g_dtbc[(size_t)ROWS * N2];
__device__ __align__(256) float g_bc  [(size_t)ROWS * 32];   // B|C f32 for scan
__device__ __align__(256) fp16  g_y2  [(size_t)ROWS * DI];
__device__ __align__(256) fp16  g_W3  [(size_t)N3 * DI];
__device__ __align__(256) float g_opre[(size_t)ROWS * DM];

// ---------------- helpers ----------------
DEVFN float h2f(fp16 v) { return __half2float(v); }
DEVFN fp16  f2h(float v) { return __float2half(v); }
DEVFN float2 h2x(uint32_t u) { h2 t = *reinterpret_cast<h2*>(&u); return __half22float2(t); }
DEVFN uint32_t pack2h(float a, float b) {
    h2 t = __floats2half2_rn(a, b);
    return *reinterpret_cast<uint32_t*>(&t);
}
DEVFN float ex2f(float x) { float r; asm("ex2.approx.f32 %0, %1;" : "=f"(r) : "f"(x)); return r; }
DEVFN float clip10(float x) { return fminf(fmaxf(x, -10.f), 10.f); }
DEVFN float sigm(float x) { return 1.f / (1.f + __expf(-x)); }

DEVFN void cp16(void* s, const void* g) {
    unsigned sa = (unsigned)__cvta_generic_to_shared(s);
    asm volatile("cp.async.cg.shared.global [%0], [%1], 16;\n" :: "r"(sa), "l"(g));
}
DEVFN void cp_commit() { asm volatile("cp.async.commit_group;\n"); }
DEVFN void ldm4(uint32_t* r, const void* p) {
    unsigned a = (unsigned)__cvta_generic_to_shared(p);
    asm volatile("ldmatrix.sync.aligned.m8n8.x4.shared.b16 {%0,%1,%2,%3}, [%4];\n"
                 : "=r"(r[0]), "=r"(r[1]), "=r"(r[2]), "=r"(r[3]) : "r"(a));
}
// fp16 inputs, fp16 accumulators (2 regs)
DEVFN void mma_h(uint32_t* c, const uint32_t* a, const uint32_t* b) {
    asm volatile(
        "mma.sync.aligned.m16n8k16.row.col.f16.f16.f16.f16 "
        "{%0,%1}, {%2,%3,%4,%5}, {%6,%7}, {%0,%1};\n"
        : "+r"(c[0]), "+r"(c[1])
        : "r"(a[0]), "r"(a[1]), "r"(a[2]), "r"(a[3]), "r"(b[0]), "r"(b[1]));
}

// ---------------- merged prep kernel ----------------
constexpr int SG0 = N1 * DM;
constexpr int SG1 = N3 * DI;
constexpr int SG2 = N2 * DI;
constexpr int SG3 = N2;
constexpr int SG4 = ROWS * DM / 4;
constexpr int PREP_TOT = SG0 + SG1 + SG2 + SG3 + SG4;

__global__ void k_prep(const float* __restrict__ Win, const float* __restrict__ Wout,
                       const float* __restrict__ Wdt, const float* __restrict__ Wx,
                       const float* __restrict__ bdt, const float* __restrict__ x) {
    int i = blockIdx.x * 256 + threadIdx.x;
    if (i < SG0) { g_W1[i] = f2h(Win[i]); return; }
    i -= SG0;
    if (i < SG1) { g_W3[i] = f2h(Wout[i]); return; }
    i -= SG1;
    if (i < SG2) {
        int n = i / DI, k = i % DI;
        float v = 0.f;
        if (n < 1024)       v = Wdt[n * DI + k];
        else if (n < 1056)  v = Wx[(n - 1024) * DI + k];   // natural B | C order
        g_Wcat[i] = f2h(v);
        return;
    }
    i -= SG2;
    if (i < SG3) { g_b2[i] = (i < 1024) ? bdt[i] : 0.f; return; }
    i -= SG3;
    if (i < SG4) {
        float4 v = *reinterpret_cast<const float4*>(x + (size_t)i * 4);
        uint2 pk;
        pk.x = pack2h(clip10(v.x), clip10(v.y));
        pk.y = pack2h(clip10(v.z), clip10(v.w));
        *reinterpret_cast<uint2*>(g_xb + (size_t)i * 4) = pk;
    }
}

// =====================================================================
// HMMA GEMM, fp16 accumulators everywhere, K-slab 32, STG=3,
// single barrier per slab, fill-after-compute, exact commit accounting.
// SEL 1/2: CTA 256x128, warp 64x64 (8 warps 4x2), 2 CTA/SM.
// SEL 3  : CTA 128x128, warp 32x64 (8 warps 4x2), 3 CTA/SM.
// =====================================================================
constexpr int STG = 3;
constexpr int SCOLS = 40;
constexpr int B_STAGE = 128 * SCOLS;
constexpr int SMEM_12 = STG * (256 + 128) * SCOLS * 2;   // 92160 B
constexpr int SMEM_3  = STG * (128 + 128) * SCOLS * 2;   // 61440 B

template <int SEL>
__global__ void __launch_bounds__(256, (SEL == 3) ? 3 : 2)
k_gemm(const float* __restrict__ resid)
{
    constexpr int N = (SEL == 1) ? N1 : (SEL == 2) ? N2 : N3;
    constexpr int K = (SEL == 1) ? DM : DI;
    constexpr int KT = K / 32;
    constexpr int MT = (SEL == 3) ? 128 : 256;            // CTA M tile
    constexpr int MW = MT / 4;                            // warp M tile
    constexpr int MI = MW / 16;                           // m16 frags per warp
    constexpr int A_STAGE = MT * SCOLS;
    const fp16* __restrict__ A  = (SEL == 1) ? g_xb : (SEL == 2) ? g_xc : g_y2;
    const fp16* __restrict__ Bw = (SEL == 1) ? g_W1 : (SEL == 2) ? g_Wcat : g_W3;

    extern __shared__ __align__(16) fp16 sm[];
    fp16* Asm = sm;
    fp16* Bsm = sm + STG * A_STAGE;

    const int tid = threadIdx.x, lane = tid & 31, warp = tid >> 5;
    const int wm = warp >> 1, wn = warp & 1;              // 4 x 2 warp grid
    const int m0 = blockIdx.y * MT, n0 = blockIdx.x * 128;
    const fp16* Ap = A + (size_t)m0 * K;
    const fp16* Bp = Bw + (size_t)n0 * K;

    uint32_t acc[MI][8][2];
#pragma unroll
    for (int i = 0; i < MI; i++)
#pragma unroll
        for (int j = 0; j < 8; j++) { acc[i][j][0] = 0u; acc[i][j][1] = 0u; }

    auto fill = [&](int kt) {
        const int buf = kt % STG;
        fp16* As = Asm + buf * A_STAGE;
        fp16* Bs = Bsm + buf * B_STAGE;
#pragma unroll
        for (int i = 0; i < MT / 64; i++) {               // A: MT*4 chunks
            int c = tid + i * 256;
            int row = c >> 2, col = (c & 3) << 3;
            cp16(As + row * SCOLS + col, Ap + (size_t)row * K + kt * 32 + col);
        }
#pragma unroll
        for (int i = 0; i < 2; i++) {                     // B: 512 chunks
            int c = tid + i * 256;
            int row = c >> 2, col = (c & 3) << 3;
            cp16(Bs + row * SCOLS + col, Bp + (size_t)row * K + kt * 32 + col);
        }
        cp_commit();
    };

    fill(0); fill(1);

#pragma unroll 1
    for (int kt = 0; kt < KT; kt++) {
        asm volatile("cp.async.wait_group 1;\n");
        __syncthreads();                                  // single barrier per slab
        const int buf = kt % STG;
        const fp16* As = Asm + buf * A_STAGE;
        const fp16* Bs = Bsm + buf * B_STAGE;
#pragma unroll
        for (int kh = 0; kh < 2; kh++) {
            const int kk = kh * 16;
            uint32_t af[MI][4], bfr[8][2];
#pragma unroll
            for (int mi = 0; mi < MI; mi++)
                ldm4(af[mi], As + (wm * MW + mi * 16 + (lane & 15)) * SCOLS
                              + kk + ((lane >> 4) << 3));
#pragma unroll
            for (int ni2 = 0; ni2 < 4; ni2++) {
                uint32_t r[4];
                ldm4(r, Bs + (wn * 64 + ni2 * 16 + (lane & 15)) * SCOLS
                         + kk + ((lane >> 4) << 3));
                bfr[2 * ni2][0] = r[0]; bfr[2 * ni2][1] = r[2];
                bfr[2 * ni2 + 1][0] = r[1]; bfr[2 * ni2 + 1][1] = r[3];
            }
#pragma unroll
            for (int mi = 0; mi < MI; mi++)
#pragma unroll
                for (int ni = 0; ni < 8; ni++)
                    mma_h(acc[mi][ni], af[mi], bfr[ni]);
        }
        // fill after compute; target buf (kt-1)%3 is free (top-barrier argument)
        if (kt + STG - 1 < KT) fill(kt + STG - 1);
        else cp_commit();
    }

    // epilogue
    const bool resHalf = (SEL == 1) && (n0 >= 1024);      // uniform per CTA
#pragma unroll
    for (int mi = 0; mi < MI; mi++) {
#pragma unroll
        for (int ni = 0; ni < 8; ni++) {
            int mA = m0 + wm * MW + mi * 16 + (lane >> 2);
            int n = n0 + wn * 64 + ni * 8 + ((lane & 3) << 1);
#pragma unroll
            for (int h = 0; h < 2; h++) {
                int mm = mA + h * 8;
                size_t idx = (size_t)mm * N + n;
                float2 t = h2x(acc[mi][ni][h]);
                float v0 = t.x, v1 = t.y;
                if (SEL == 1) {
                    if (resHalf) { v0 *= sigm(v0); v1 *= sigm(v1); }   // pre-silu res
                    *reinterpret_cast<uint32_t*>(g_xr + idx) = pack2h(v0, v1);
                } else if (SEL == 2) {
                    v0 += g_b2[n]; v1 += g_b2[n + 1];
                    *reinterpret_cast<uint32_t*>(g_dtbc + idx) = pack2h(v0, v1);
                    if (n >= 1024 && n < 1056)
                        *reinterpret_cast<float2*>(&g_bc[(size_t)mm * 32 + (n - 1024)]) =
                            make_float2(v0, v1);
                } else {
                    float x0 = clip10(resid[idx]);
                    float x1 = clip10(resid[idx + 1]);
                    *reinterpret_cast<float2*>(g_opre + idx) = make_float2(v0 + x0, v1 + x1);
                }
            }
        }
    }
}

// ---------------- causal depthwise conv(4) + SiLU, 4 di / thread --------
__global__ void k_conv(const float* __restrict__ cw, const float* __restrict__ cb) {
    int idx = blockIdx.x * 256 + threadIdx.x;
    if (idx >= ROWS * (DI / 4)) return;
    int di4 = (idx & 255) * 4;
    size_t row = (size_t)(idx >> 8);
    int t = (int)(row % SEQ);

    float acc[4] = { cb[di4], cb[di4 + 1], cb[di4 + 2], cb[di4 + 3] };
    float4 w0 = *reinterpret_cast<const float4*>(cw + (di4 + 0) * 4);
    float4 w1 = *reinterpret_cast<const float4*>(cw + (di4 + 1) * 4);
    float4 w2 = *reinterpret_cast<const float4*>(cw + (di4 + 2) * 4);
    float4 w3 = *reinterpret_cast<const float4*>(cw + (di4 + 3) * 4);
    const float* wv[4] = { (const float*)&w0, (const float*)&w1,
                           (const float*)&w2, (const float*)&w3 };
#pragma unroll
    for (int k = 0; k < 4; k++) {
        if (t - 3 + k < 0) continue;
        uint2 raw = *reinterpret_cast<const uint2*>(&g_xr[(row - 3 + k) * N1 + di4]);
        float2 lo = h2x(raw.x), hi = h2x(raw.y);
        acc[0] = fmaf(wv[0][k], lo.x, acc[0]);
        acc[1] = fmaf(wv[1][k], lo.y, acc[1]);
        acc[2] = fmaf(wv[2][k], hi.x, acc[2]);
        acc[3] = fmaf(wv[3][k], hi.y, acc[3]);
    }
#pragma unroll
    for (int j = 0; j < 4; j++) acc[j] = acc[j] * sigm(acc[j]);
    uint2 pk;
    pk.x = pack2h(acc[0], acc[1]);
    pk.y = pack2h(acc[2], acc[3]);
    *reinterpret_cast<uint2*>(&g_xc[row * DI + di4]) = pk;
}

// =====================================================================
// Selective scan: 64-thread blocks (16 di x 4 q), 1024 blocks,
// cp.async ring, f32 B/C, pre-silu'ed res, fused output. Chunk 16 t.
// Per t in smem (224B): dt 32B | u 32B | B 64B f32 | C 64B f32 | res 32B
// =====================================================================
constexpr int SC_CHUNK = 16;
constexpr int SC_RING = 4;
constexpr int SC_TB = 224;
constexpr int SC_CHB = SC_CHUNK * SC_TB;                  // 3584 B
constexpr int SC_NCH = SEQ / SC_CHUNK;                    // 128

__global__ void __launch_bounds__(64) k_scan(const float* __restrict__ A_log,
                                             const float* __restrict__ Dp) {
    __shared__ __align__(16) char sbuf[SC_RING * SC_CHB]; // 14336 B

    const int tid = threadIdx.x;
    const int b = blockIdx.x >> 6;
    const int diblk = blockIdx.x & 63;
    const int q = tid & 3;
    const int dil = tid >> 2;                             // 0..15
    const int di = diblk * 16 + dil;
    const float LOG2E = 1.4426950408889634f;

    float A2[4];
#pragma unroll
    for (int j = 0; j < 4; j++) A2[j] = A_log[q * 4 + j] * LOG2E;
    const float Dv = Dp[di];
    const size_t rb = (size_t)b * SEQ;

    auto fill = [&](int c) {
#pragma unroll
        for (int r = 0; r < 4; r++) {
            int cc = tid + r * 64;                        // 0..255
            if (cc < 14 * SC_CHUNK) {                     // 14 cp16 per t
                int t = cc / 14, part = cc % 14;
                size_t row = rb + (size_t)c * SC_CHUNK + t;
                char* dst = sbuf + (c & (SC_RING - 1)) * SC_CHB + t * SC_TB;
                const char* src;
                if (part < 2) {
                    dst += part * 16;
                    src = (const char*)&g_dtbc[row * N2 + diblk * 16] + part * 16;
                } else if (part < 4) {
                    dst += 32 + (part - 2) * 16;
                    src = (const char*)&g_xc[row * DI + diblk * 16] + (part - 2) * 16;
                } else if (part < 12) {
                    dst += 64 + (part - 4) * 16;
                    src = (const char*)&g_bc[row * 32] + (part - 4) * 16;
                } else {
                    dst += 192 + (part - 12) * 16;
                    src = (const char*)&g_xr[row * N1 + 1024 + diblk * 16] + (part - 12) * 16;
                }
                cp16(dst, src);
            }
        }
        cp_commit();
    };

    fill(0); fill(1); fill(2);

    float s0 = 0.f, s1 = 0.f, s2 = 0.f, s3 = 0.f;

#pragma unroll 1
    for (int c = 0; c < SC_NCH; c++) {
        asm volatile("cp.async.wait_group %0;\n" :: "n"(2));
        __syncthreads();
        const char* base = sbuf + (c & (SC_RING - 1)) * SC_CHB;
#pragma unroll
        for (int tl = 0; tl < SC_CHUNK; tl++) {
            const char* p = base + tl * SC_TB;
            float dt = h2f(reinterpret_cast<const fp16*>(p)[dil]);
            float u  = h2f(reinterpret_cast<const fp16*>(p + 32)[dil]);
            float4 B4 = *reinterpret_cast<const float4*>(p + 64 + q * 16);
            float4 C4 = *reinterpret_cast<const float4*>(p + 128 + q * 16);
            float du = dt * u;

            float acc;
            s0 = fmaf(ex2f(dt * A2[0]), s0, du * B4.x); acc = s0 * C4.x;
            s1 = fmaf(ex2f(dt * A2[1]), s1, du * B4.y); acc = fmaf(s1, C4.y, acc);
            s2 = fmaf(ex2f(dt * A2[2]), s2, du * B4.z); acc = fmaf(s2, C4.z, acc);
            s3 = fmaf(ex2f(dt * A2[3]), s3, du * B4.w); acc = fmaf(s3, C4.w, acc);

            acc += __shfl_xor_sync(0xffffffffu, acc, 1);
            acc += __shfl_xor_sync(0xffffffffu, acc, 2);
            if (q == 0) {
                float rp = h2f(reinterpret_cast<const fp16*>(p + 192)[dil]);  // pre-silu'ed
                g_y2[(rb + (size_t)c * SC_CHUNK + tl) * DI + di] =
                    f2h(fmaf(u, Dv, acc) * rp);
            }
        }
        if (c + 3 < SC_NCH) fill(c + 3);
        else cp_commit();
    }
}

// ---------------- LayerNorm ----------------
__global__ void __launch_bounds__(256) k_ln(const float* __restrict__ gam,
                                            const float* __restrict__ bet,
                                            float* __restrict__ out) {
    int w = (blockIdx.x * 256 + threadIdx.x) >> 5;
    int lane = threadIdx.x & 31;
    if (w >= ROWS) return;
    const float* r = g_opre + (size_t)w * DM;
    float v[16], s = 0.f, ss = 0.f;
#pragma unroll
    for (int i = 0; i < 16; i++) {
        v[i] = r[i * 32 + lane];
        s += v[i];
        ss = fmaf(v[i], v[i], ss);
    }
#pragma unroll
    for (int o = 16; o; o >>= 1) {
        s += __shfl_xor_sync(0xffffffffu, s, o);
        ss += __shfl_xor_sync(0xffffffffu, ss, o);
    }
    float mu = s * (1.f / 512.f);
    float var = ss * (1.f / 512.f) - mu * mu;
    float rstd = rsqrtf(var + 1e-5f);
#pragma unroll
    for (int i = 0; i < 16; i++) {
        int c = i * 32 + lane;
        out[(size_t)w * DM + c] = (v[i] - mu) * rstd * gam[c] + bet[c];
    }
}

// ---------------- launch ----------------
extern "C" void kernel_launch(void* const* d_in, const int* in_sizes, int n_in,
                              void* d_out, int out_size) {
    const float* x      = (const float*)d_in[0];
    const float* W_in   = (const float*)d_in[1];
    const float* conv_w = (const float*)d_in[2];
    const float* conv_b = (const float*)d_in[3];
    const float* W_x    = (const float*)d_in[4];
    const float* W_dt   = (const float*)d_in[5];
    const float* b_dt   = (const float*)d_in[6];
    const float* A_log  = (const float*)d_in[7];
    const float* Dp     = (const float*)d_in[8];
    const float* W_out  = (const float*)d_in[9];
    const float* ln_g   = (const float*)d_in[10];
    const float* ln_b   = (const float*)d_in[11];
    float* out = (float*)d_out;

    static bool attr_done = false;
    if (!attr_done) {
        cudaFuncSetAttribute(k_gemm<1>, cudaFuncAttributeMaxDynamicSharedMemorySize, SMEM_12);
        cudaFuncSetAttribute(k_gemm<2>, cudaFuncAttributeMaxDynamicSharedMemorySize, SMEM_12);
        cudaFuncSetAttribute(k_gemm<3>, cudaFuncAttributeMaxDynamicSharedMemorySize, SMEM_3);
        attr_done = true;
    }

    // 1: prep
    k_prep<<<(PREP_TOT + 255) / 256, 256>>>(W_in, W_out, W_dt, W_x, b_dt, x);
    // 2: GEMM1 [32768,2048] 256-tile fp16-acc (res half pre-silu'ed)
    k_gemm<1><<<dim3(N1 / 128, ROWS / 256), 256, SMEM_12>>>(nullptr);
    // 3: conv
    k_conv<<<ROWS * (DI / 4) / 256, 256>>>(conv_w, conv_b);
    // 4: GEMM2 [32768,1152] 256-tile fp16-acc (+f32 BC side-store)  <-- ncu window
    k_gemm<2><<<dim3(N2 / 128, ROWS / 256), 256, SMEM_12>>>(nullptr);
    // 5: scan (+ fused mulsilu) -> g_y2
    k_scan<<<B_SZ * 64, 64>>>(A_log, Dp);
    // 6: GEMM3 [32768,512] 128-tile fp16-acc + f32 residual
    k_gemm<3><<<dim3(N3 / 128, ROWS / 128), 256, SMEM_3>>>(x);
    // 7: LN
    k_ln<<<(ROWS * 32 + 255) / 256, 256>>>(ln_g, ln_b, out);
}

// round 14
// speedup vs baseline: 2.8037x; 1.0010x over previous
#include <cuda_runtime.h>
#include <cuda_fp16.h>
#include <cstdint>

using fp16 = __half;
using h2 = __half2;

#define DEVFN __device__ __forceinline__

// ---------------- problem sizes ----------------
constexpr int B_SZ = 16, SEQ = 2048, DM = 512, DI = 1024, DS = 16;
constexpr int ROWS = B_SZ * SEQ;           // 32768
constexpr int N1 = 2 * DI;                 // 2048
constexpr int N2 = 1152;                   // 1024 dt + 32 (B|C) + 96 pad
constexpr int N3 = DM;                     // 512

// ---------------- scratch globals (fp16 intermediates) ----------------
__device__ __align__(256) fp16  g_xb  [(size_t)ROWS * DM];
__device__ __align__(256) fp16  g_W1  [(size_t)N1 * DM];
__device__ __align__(256) fp16  g_xr  [(size_t)ROWS * N1];   // x_p | silu(res)
__device__ __align__(256) fp16  g_xc  [(size_t)ROWS * DI];
__device__ __align__(256) fp16  g_Wcat[(size_t)N2 * DI];
__device__ __align__(256) float g_b2  [N2];
__device__ __align__(256) fp16  g_dtbc[(size_t)ROWS * N2];
__device__ __align__(256) float g_bc  [(size_t)ROWS * 32];   // B|C f32 for scan
__device__ __align__(256) fp16  g_y2  [(size_t)ROWS * DI];
__device__ __align__(256) fp16  g_W3  [(size_t)N3 * DI];
__device__ __align__(256) float g_opre[(size_t)ROWS * DM];

// ---------------- helpers ----------------
DEVFN float h2f(fp16 v) { return __half2float(v); }
DEVFN fp16  f2h(float v) { return __float2half(v); }
DEVFN float2 h2x(uint32_t u) { h2 t = *reinterpret_cast<h2*>(&u); return __half22float2(t); }
DEVFN uint32_t pack2h(float a, float b) {
    h2 t = __floats2half2_rn(a, b);
    return *reinterpret_cast<uint32_t*>(&t);
}
DEVFN float ex2f(float x) { float r; asm("ex2.approx.f32 %0, %1;" : "=f"(r) : "f"(x)); return r; }
DEVFN float clip10(float x) { return fminf(fmaxf(x, -10.f), 10.f); }
DEVFN float sigm(float x) { return 1.f / (1.f + __expf(-x)); }

DEVFN void cp16(void* s, const void* g) {
    unsigned sa = (unsigned)__cvta_generic_to_shared(s);
    asm volatile("cp.async.cg.shared.global [%0], [%1], 16;\n" :: "r"(sa), "l"(g));
}
DEVFN void cp_commit() { asm volatile("cp.async.commit_group;\n"); }
DEVFN void ldm4(uint32_t* r, const void* p) {
    unsigned a = (unsigned)__cvta_generic_to_shared(p);
    asm volatile("ldmatrix.sync.aligned.m8n8.x4.shared.b16 {%0,%1,%2,%3}, [%4];\n"
                 : "=r"(r[0]), "=r"(r[1]), "=r"(r[2]), "=r"(r[3]) : "r"(a));
}
// fp16 inputs, fp16 accumulators (2 regs)
DEVFN void mma_h(uint32_t* c, const uint32_t* a, const uint32_t* b) {
    asm volatile(
        "mma.sync.aligned.m16n8k16.row.col.f16.f16.f16.f16 "
        "{%0,%1}, {%2,%3,%4,%5}, {%6,%7}, {%0,%1};\n"
        : "+r"(c[0]), "+r"(c[1])
        : "r"(a[0]), "r"(a[1]), "r"(a[2]), "r"(a[3]), "r"(b[0]), "r"(b[1]));
}

// ---------------- merged prep kernel ----------------
constexpr int SG0 = N1 * DM;
constexpr int SG1 = N3 * DI;
constexpr int SG2 = N2 * DI;
constexpr int SG3 = N2;
constexpr int SG4 = ROWS * DM / 4;
constexpr int PREP_TOT = SG0 + SG1 + SG2 + SG3 + SG4;

__global__ void k_prep(const float* __restrict__ Win, const float* __restrict__ Wout,
                       const float* __restrict__ Wdt, const float* __restrict__ Wx,
                       const float* __restrict__ bdt, const float* __restrict__ x) {
    int i = blockIdx.x * 256 + threadIdx.x;
    if (i < SG0) { g_W1[i] = f2h(Win[i]); return; }
    i -= SG0;
    if (i < SG1) { g_W3[i] = f2h(Wout[i]); return; }
    i -= SG1;
    if (i < SG2) {
        int n = i / DI, k = i % DI;
        float v = 0.f;
        if (n < 1024)       v = Wdt[n * DI + k];
        else if (n < 1056)  v = Wx[(n - 1024) * DI + k];   // natural B | C order
        g_Wcat[i] = f2h(v);
        return;
    }
    i -= SG2;
    if (i < SG3) { g_b2[i] = (i < 1024) ? bdt[i] : 0.f; return; }
    i -= SG3;
    if (i < SG4) {
        float4 v = *reinterpret_cast<const float4*>(x + (size_t)i * 4);
        uint2 pk;
        pk.x = pack2h(clip10(v.x), clip10(v.y));
        pk.y = pack2h(clip10(v.z), clip10(v.w));
        *reinterpret_cast<uint2*>(g_xb + (size_t)i * 4) = pk;
    }
}

// =====================================================================
// HMMA GEMM — CTA 128x128, warp 32x64 (8 warps 4x2), fp16 accumulators,
// K-slab 64 (SCOLS=72), STG=3, 2 CTA/SM, single barrier per slab,
// fill-after-compute, exact commit accounting.
// =====================================================================
constexpr int STG = 3;
constexpr int KS = 64;                     // K-slab
constexpr int SCOLS = 72;                  // 64 + 8 pad
constexpr int A_STAGE = 128 * SCOLS;
constexpr int B_STAGE = 128 * SCOLS;
constexpr int SMEM_G = STG * (A_STAGE + B_STAGE) * 2;    // 110592 B

template <int SEL>
__global__ void __launch_bounds__(256, 2) k_gemm(const float* __restrict__ resid)
{
    constexpr int N = (SEL == 1) ? N1 : (SEL == 2) ? N2 : N3;
    constexpr int K = (SEL == 1) ? DM : DI;
    constexpr int KT = K / KS;             // 8 or 16
    const fp16* __restrict__ A  = (SEL == 1) ? g_xb : (SEL == 2) ? g_xc : g_y2;
    const fp16* __restrict__ Bw = (SEL == 1) ? g_W1 : (SEL == 2) ? g_Wcat : g_W3;

    extern __shared__ __align__(16) fp16 sm[];
    fp16* Asm = sm;
    fp16* Bsm = sm + STG * A_STAGE;

    const int tid = threadIdx.x, lane = tid & 31, warp = tid >> 5;
    const int wm = warp >> 1, wn = warp & 1;              // 4 x 2 warp grid
    const int m0 = blockIdx.y * 128, n0 = blockIdx.x * 128;
    const fp16* Ap = A + (size_t)m0 * K;
    const fp16* Bp = Bw + (size_t)n0 * K;

    uint32_t acc[2][8][2];
#pragma unroll
    for (int i = 0; i < 2; i++)
#pragma unroll
        for (int j = 0; j < 8; j++) { acc[i][j][0] = 0u; acc[i][j][1] = 0u; }

    auto fill = [&](int kt) {
        const int buf = kt % STG;
        fp16* As = Asm + buf * A_STAGE;
        fp16* Bs = Bsm + buf * B_STAGE;
#pragma unroll
        for (int i = 0; i < 4; i++) {                     // A: 1024 chunks
            int c = tid + i * 256;
            int row = c >> 3, col = (c & 7) << 3;
            cp16(As + row * SCOLS + col, Ap + (size_t)row * K + kt * KS + col);
        }
#pragma unroll
        for (int i = 0; i < 4; i++) {                     // B: 1024 chunks
            int c = tid + i * 256;
            int row = c >> 3, col = (c & 7) << 3;
            cp16(Bs + row * SCOLS + col, Bp + (size_t)row * K + kt * KS + col);
        }
        cp_commit();
    };

    fill(0); fill(1);

#pragma unroll 1
    for (int kt = 0; kt < KT; kt++) {
        asm volatile("cp.async.wait_group 1;\n");
        __syncthreads();                                  // single barrier per slab
        const int buf = kt % STG;
        const fp16* As = Asm + buf * A_STAGE;
        const fp16* Bs = Bsm + buf * B_STAGE;
#pragma unroll
        for (int kh = 0; kh < 4; kh++) {
            const int kk = kh * 16;
            uint32_t af[2][4], bfr[8][2];
#pragma unroll
            for (int mi = 0; mi < 2; mi++)
                ldm4(af[mi], As + (wm * 32 + mi * 16 + (lane & 15)) * SCOLS
                              + kk + ((lane >> 4) << 3));
#pragma unroll
            for (int ni2 = 0; ni2 < 4; ni2++) {
                uint32_t r[4];
                ldm4(r, Bs + (wn * 64 + ni2 * 16 + (lane & 15)) * SCOLS
                         + kk + ((lane >> 4) << 3));
                bfr[2 * ni2][0] = r[0]; bfr[2 * ni2][1] = r[2];
                bfr[2 * ni2 + 1][0] = r[1]; bfr[2 * ni2 + 1][1] = r[3];
            }
#pragma unroll
            for (int mi = 0; mi < 2; mi++)
#pragma unroll
                for (int ni = 0; ni < 8; ni++)
                    mma_h(acc[mi][ni], af[mi], bfr[ni]);
        }
        // fill after compute; target buf (kt-1)%3 is free (top-barrier argument)
        if (kt + STG - 1 < KT) fill(kt + STG - 1);
        else cp_commit();
    }

    // epilogue
    const bool resHalf = (SEL == 1) && (n0 >= 1024);      // uniform per CTA
#pragma unroll
    for (int mi = 0; mi < 2; mi++) {
#pragma unroll
        for (int ni = 0; ni < 8; ni++) {
            int mA = m0 + wm * 32 + mi * 16 + (lane >> 2);
            int n = n0 + wn * 64 + ni * 8 + ((lane & 3) << 1);
#pragma unroll
            for (int h = 0; h < 2; h++) {
                int mm = mA + h * 8;
                size_t idx = (size_t)mm * N + n;
                if (SEL == 1) {
                    if (resHalf) {
                        float2 t = h2x(acc[mi][ni][h]);
                        float v0 = t.x * sigm(t.x), v1 = t.y * sigm(t.y);
                        *reinterpret_cast<uint32_t*>(g_xr + idx) = pack2h(v0, v1);
                    } else {
                        // x_p half: raw packed fp16 accumulator store
                        *reinterpret_cast<uint32_t*>(g_xr + idx) = acc[mi][ni][h];
                    }
                } else if (SEL == 2) {
                    float2 t = h2x(acc[mi][ni][h]);
                    float v0 = t.x + g_b2[n], v1 = t.y + g_b2[n + 1];
                    *reinterpret_cast<uint32_t*>(g_dtbc + idx) = pack2h(v0, v1);
                    if (n >= 1024 && n < 1056)
                        *reinterpret_cast<float2*>(&g_bc[(size_t)mm * 32 + (n - 1024)]) =
                            make_float2(v0, v1);
                } else {
                    float2 t = h2x(acc[mi][ni][h]);
                    float x0 = clip10(resid[idx]);
                    float x1 = clip10(resid[idx + 1]);
                    *reinterpret_cast<float2*>(g_opre + idx) =
                        make_float2(t.x + x0, t.y + x1);
                }
            }
        }
    }
}

// ---------------- causal depthwise conv(4) + SiLU, 4 di / thread --------
__global__ void k_conv(const float* __restrict__ cw, const float* __restrict__ cb) {
    int idx = blockIdx.x * 256 + threadIdx.x;
    if (idx >= ROWS * (DI / 4)) return;
    int di4 = (idx & 255) * 4;
    size_t row = (size_t)(idx >> 8);
    int t = (int)(row % SEQ);

    float acc[4] = { cb[di4], cb[di4 + 1], cb[di4 + 2], cb[di4 + 3] };
    float4 w0 = *reinterpret_cast<const float4*>(cw + (di4 + 0) * 4);
    float4 w1 = *reinterpret_cast<const float4*>(cw + (di4 + 1) * 4);
    float4 w2 = *reinterpret_cast<const float4*>(cw + (di4 + 2) * 4);
    float4 w3 = *reinterpret_cast<const float4*>(cw + (di4 + 3) * 4);
    const float* wv[4] = { (const float*)&w0, (const float*)&w1,
                           (const float*)&w2, (const float*)&w3 };
#pragma unroll
    for (int k = 0; k < 4; k++) {
        if (t - 3 + k < 0) continue;
        uint2 raw = *reinterpret_cast<const uint2*>(&g_xr[(row - 3 + k) * N1 + di4]);
        float2 lo = h2x(raw.x), hi = h2x(raw.y);
        acc[0] = fmaf(wv[0][k], lo.x, acc[0]);
        acc[1] = fmaf(wv[1][k], lo.y, acc[1]);
        acc[2] = fmaf(wv[2][k], hi.x, acc[2]);
        acc[3] = fmaf(wv[3][k], hi.y, acc[3]);
    }
#pragma unroll
    for (int j = 0; j < 4; j++) acc[j] = acc[j] * sigm(acc[j]);
    uint2 pk;
    pk.x = pack2h(acc[0], acc[1]);
    pk.y = pack2h(acc[2], acc[3]);
    *reinterpret_cast<uint2*>(&g_xc[row * DI + di4]) = pk;
}

// =====================================================================
// Selective scan: 64-thread blocks (16 di x 4 q), 1024 blocks,
// cp.async ring, f32 B/C, pre-silu'ed res, fused output. Chunk 16 t.
// Per t in smem (224B): dt 32B | u 32B | B 64B f32 | C 64B f32 | res 32B
// =====================================================================
constexpr int SC_CHUNK = 16;
constexpr int SC_RING = 4;
constexpr int SC_TB = 224;
constexpr int SC_CHB = SC_CHUNK * SC_TB;                  // 3584 B
constexpr int SC_NCH = SEQ / SC_CHUNK;                    // 128

__global__ void __launch_bounds__(64) k_scan(const float* __restrict__ A_log,
                                             const float* __restrict__ Dp) {
    __shared__ __align__(16) char sbuf[SC_RING * SC_CHB]; // 14336 B

    const int tid = threadIdx.x;
    const int b = blockIdx.x >> 6;
    const int diblk = blockIdx.x & 63;
    const int q = tid & 3;
    const int dil = tid >> 2;                             // 0..15
    const int di = diblk * 16 + dil;
    const float LOG2E = 1.4426950408889634f;

    float A2[4];
#pragma unroll
    for (int j = 0; j < 4; j++) A2[j] = A_log[q * 4 + j] * LOG2E;
    const float Dv = Dp[di];
    const size_t rb = (size_t)b * SEQ;

    auto fill = [&](int c) {
#pragma unroll
        for (int r = 0; r < 4; r++) {
            int cc = tid + r * 64;                        // 0..255
            if (cc < 14 * SC_CHUNK) {                     // 14 cp16 per t
                int t = cc / 14, part = cc % 14;
                size_t row = rb + (size_t)c * SC_CHUNK + t;
                char* dst = sbuf + (c & (SC_RING - 1)) * SC_CHB + t * SC_TB;
                const char* src;
                if (part < 2) {
                    dst += part * 16;
                    src = (const char*)&g_dtbc[row * N2 + diblk * 16] + part * 16;
                } else if (part < 4) {
                    dst += 32 + (part - 2) * 16;
                    src = (const char*)&g_xc[row * DI + diblk * 16] + (part - 2) * 16;
                } else if (part < 12) {
                    dst += 64 + (part - 4) * 16;
                    src = (const char*)&g_bc[row * 32] + (part - 4) * 16;
                } else {
                    dst += 192 + (part - 12) * 16;
                    src = (const char*)&g_xr[row * N1 + 1024 + diblk * 16] + (part - 12) * 16;
                }
                cp16(dst, src);
            }
        }
        cp_commit();
    };

    fill(0); fill(1); fill(2);

    float s0 = 0.f, s1 = 0.f, s2 = 0.f, s3 = 0.f;

#pragma unroll 1
    for (int c = 0; c < SC_NCH; c++) {
        asm volatile("cp.async.wait_group %0;\n" :: "n"(2));
        __syncthreads();
        const char* base = sbuf + (c & (SC_RING - 1)) * SC_CHB;
#pragma unroll
        for (int tl = 0; tl < SC_CHUNK; tl++) {
            const char* p = base + tl * SC_TB;
            float dt = h2f(reinterpret_cast<const fp16*>(p)[dil]);
            float u  = h2f(reinterpret_cast<const fp16*>(p + 32)[dil]);
            float4 B4 = *reinterpret_cast<const float4*>(p + 64 + q * 16);
            float4 C4 = *reinterpret_cast<const float4*>(p + 128 + q * 16);
            float du = dt * u;

            float acc;
            s0 = fmaf(ex2f(dt * A2[0]), s0, du * B4.x); acc = s0 * C4.x;
            s1 = fmaf(ex2f(dt * A2[1]), s1, du * B4.y); acc = fmaf(s1, C4.y, acc);
            s2 = fmaf(ex2f(dt * A2[2]), s2, du * B4.z); acc = fmaf(s2, C4.z, acc);
            s3 = fmaf(ex2f(dt * A2[3]), s3, du * B4.w); acc = fmaf(s3, C4.w, acc);

            acc += __shfl_xor_sync(0xffffffffu, acc, 1);
            acc += __shfl_xor_sync(0xffffffffu, acc, 2);
            if (q == 0) {
                float rp = h2f(reinterpret_cast<const fp16*>(p + 192)[dil]);  // pre-silu'ed
                g_y2[(rb + (size_t)c * SC_CHUNK + tl) * DI + di] =
                    f2h(fmaf(u, Dv, acc) * rp);
            }
        }
        if (c + 3 < SC_NCH) fill(c + 3);
        else cp_commit();
    }
}

// ---------------- LayerNorm ----------------
__global__ void __launch_bounds__(256) k_ln(const float* __restrict__ gam,
                                            const float* __restrict__ bet,
                                            float* __restrict__ out) {
    int w = (blockIdx.x * 256 + threadIdx.x) >> 5;
    int lane = threadIdx.x & 31;
    if (w >= ROWS) return;
    const float* r = g_opre + (size_t)w * DM;
    float v[16], s = 0.f, ss = 0.f;
#pragma unroll
    for (int i = 0; i < 16; i++) {
        v[i] = r[i * 32 + lane];
        s += v[i];
        ss = fmaf(v[i], v[i], ss);
    }
#pragma unroll
    for (int o = 16; o; o >>= 1) {
        s += __shfl_xor_sync(0xffffffffu, s, o);
        ss += __shfl_xor_sync(0xffffffffu, ss, o);
    }
    float mu = s * (1.f / 512.f);
    float var = ss * (1.f / 512.f) - mu * mu;
    float rstd = rsqrtf(var + 1e-5f);
#pragma unroll
    for (int i = 0; i < 16; i++) {
        int c = i * 32 + lane;
        out[(size_t)w * DM + c] = (v[i] - mu) * rstd * gam[c] + bet[c];
    }
}

// ---------------- launch ----------------
extern "C" void kernel_launch(void* const* d_in, const int* in_sizes, int n_in,
                              void* d_out, int out_size) {
    const float* x      = (const float*)d_in[0];
    const float* W_in   = (const float*)d_in[1];
    const float* conv_w = (const float*)d_in[2];
    const float* conv_b = (const float*)d_in[3];
    const float* W_x    = (const float*)d_in[4];
    const float* W_dt   = (const float*)d_in[5];
    const float* b_dt   = (const float*)d_in[6];
    const float* A_log  = (const float*)d_in[7];
    const float* Dp     = (const float*)d_in[8];
    const float* W_out  = (const float*)d_in[9];
    const float* ln_g   = (const float*)d_in[10];
    const float* ln_b   = (const float*)d_in[11];
    float* out = (float*)d_out;

    static bool attr_done = false;
    if (!attr_done) {
        cudaFuncSetAttribute(k_gemm<1>, cudaFuncAttributeMaxDynamicSharedMemorySize, SMEM_G);
        cudaFuncSetAttribute(k_gemm<2>, cudaFuncAttributeMaxDynamicSharedMemorySize, SMEM_G);
        cudaFuncSetAttribute(k_gemm<3>, cudaFuncAttributeMaxDynamicSharedMemorySize, SMEM_G);
        attr_done = true;
    }

    // 1: prep
    k_prep<<<(PREP_TOT + 255) / 256, 256>>>(W_in, W_out, W_dt, W_x, b_dt, x);
    // 2: GEMM1 [32768,2048] k-slab 64 (res half pre-silu'ed, x_p raw-store)
    k_gemm<1><<<dim3(N1 / 128, ROWS / 128), 256, SMEM_G>>>(nullptr);
    // 3: conv
    k_conv<<<ROWS * (DI / 4) / 256, 256>>>(conv_w, conv_b);
    // 4: GEMM2 [32768,1152] k-slab 64 (+f32 BC side-store)  <-- ncu window
    k_gemm<2><<<dim3(N2 / 128, ROWS / 128), 256, SMEM_G>>>(nullptr);
    // 5: scan (+ fused mulsilu) -> g_y2
    k_scan<<<B_SZ * 64, 64>>>(A_log, Dp);
    // 6: GEMM3 [32768,512] k-slab 64 + f32 residual
    k_gemm<3><<<dim3(N3 / 128, ROWS / 128), 256, SMEM_G>>>(x);
    // 7: LN
    k_ln<<<(ROWS * 32 + 255) / 256, 256>>>(ln_g, ln_b, out);
}